// round 3
// baseline (speedup 1.0000x reference)
#include <cuda_runtime.h>
#include <math.h>

// Problem constants (B=1)
#define SEQ   2048
#define HID   4096
#define NH    32
#define NKV   8
#define HD    128
#define QDIM  (NH * HD)   // 4096
#define KVDIM (NKV * HD)  // 1024
#define RSCALE 0.08838834764831845f  // 128^-0.5
#define REPS   1e-6f

// Scratch (allocation-free rule: __device__ globals)
__device__ float g_Q[SEQ * QDIM];    // 32 MB
__device__ float g_K[SEQ * KVDIM];   // 8 MB
__device__ float g_V[SEQ * KVDIM];   // 8 MB
__device__ float g_AO[SEQ * QDIM];   // 32 MB

// ---------------------------------------------------------------------------
// SGEMM: C[M,N] = A[M,K] * W[N,K]^T   (A, W, C row-major, all dims % 128/16 == 0)
// 128x128 block tile, BK=16, 256 threads, 8x8 per-thread microtile.
// ---------------------------------------------------------------------------
__global__ __launch_bounds__(256) void sgemm_nt(
    const float* __restrict__ A, const float* __restrict__ W,
    float* __restrict__ C, int M, int N, int K)
{
    __shared__ float As[16][132];
    __shared__ float Bs[16][132];

    const int tid = threadIdx.x;
    const int tx = tid & 15;       // 0..15 -> N microtile
    const int ty = tid >> 4;       // 0..15 -> M microtile
    const int bm = blockIdx.y * 128;
    const int bn = blockIdx.x * 128;

    const float* Ab = A + (size_t)bm * K;
    const float* Wb = W + (size_t)bn * K;

    float acc[8][8];
#pragma unroll
    for (int i = 0; i < 8; i++)
#pragma unroll
        for (int j = 0; j < 8; j++) acc[i][j] = 0.0f;

    for (int kt = 0; kt < K; kt += 16) {
        // Load 128x16 of A and W into smem (transposed: [k][row])
#pragma unroll
        for (int t = 0; t < 2; t++) {
            int idx = tid + t * 256;          // 0..511
            int row = idx >> 2;               // 0..127
            int c4  = (idx & 3) << 2;         // 0,4,8,12
            float4 av = *(const float4*)(Ab + (size_t)row * K + kt + c4);
            As[c4 + 0][row] = av.x; As[c4 + 1][row] = av.y;
            As[c4 + 2][row] = av.z; As[c4 + 3][row] = av.w;
            float4 wv = *(const float4*)(Wb + (size_t)row * K + kt + c4);
            Bs[c4 + 0][row] = wv.x; Bs[c4 + 1][row] = wv.y;
            Bs[c4 + 2][row] = wv.z; Bs[c4 + 3][row] = wv.w;
        }
        __syncthreads();

#pragma unroll
        for (int k = 0; k < 16; k++) {
            float a[8], b[8];
            *(float4*)(a)     = *(const float4*)&As[k][ty * 8];
            *(float4*)(a + 4) = *(const float4*)&As[k][ty * 8 + 4];
            *(float4*)(b)     = *(const float4*)&Bs[k][tx * 8];
            *(float4*)(b + 4) = *(const float4*)&Bs[k][tx * 8 + 4];
#pragma unroll
            for (int i = 0; i < 8; i++)
#pragma unroll
                for (int j = 0; j < 8; j++)
                    acc[i][j] = fmaf(a[i], b[j], acc[i][j]);
        }
        __syncthreads();
    }

#pragma unroll
    for (int i = 0; i < 8; i++) {
        float* cp = C + (size_t)(bm + ty * 8 + i) * N + bn + tx * 8;
        float4 c0 = make_float4(acc[i][0], acc[i][1], acc[i][2], acc[i][3]);
        float4 c1 = make_float4(acc[i][4], acc[i][5], acc[i][6], acc[i][7]);
        *(float4*)cp = c0;
        *(float4*)(cp + 4) = c1;
    }
}

// ---------------------------------------------------------------------------
// Fused RMSNorm + RoPE over rows of X [S*nheads, 128], in place.
// One warp per row; lane holds 4 contiguous d-values.
// ---------------------------------------------------------------------------
__global__ __launch_bounds__(256) void rmsnorm_rope(
    float* __restrict__ X, const float* __restrict__ w,
    const float* __restrict__ cosb, const float* __restrict__ sinb,
    int nheads)
{
    const int row  = blockIdx.x * 8 + (threadIdx.x >> 5);
    const int lane = threadIdx.x & 31;
    const int s    = row / nheads;

    float* x = X + (size_t)row * HD;
    float4 v = *(const float4*)(x + lane * 4);

    float ss = v.x * v.x + v.y * v.y + v.z * v.z + v.w * v.w;
#pragma unroll
    for (int o = 16; o > 0; o >>= 1) ss += __shfl_xor_sync(0xffffffffu, ss, o);
    const float inv = rsqrtf(ss * (1.0f / 128.0f) + REPS);

    float4 wv = *(const float4*)(w + lane * 4);
    float x0 = v.x * inv * wv.x;
    float x1 = v.y * inv * wv.y;
    float x2 = v.z * inv * wv.z;
    float x3 = v.w * inv * wv.w;

    // rotate_half partner lives 16 lanes away (d +/- 64)
    float p0 = __shfl_xor_sync(0xffffffffu, x0, 16);
    float p1 = __shfl_xor_sync(0xffffffffu, x1, 16);
    float p2 = __shfl_xor_sync(0xffffffffu, x2, 16);
    float p3 = __shfl_xor_sync(0xffffffffu, x3, 16);
    const float sgn = (lane < 16) ? -1.0f : 1.0f;

    const float* cp = cosb + (size_t)s * HD + lane * 4;
    const float* sp = sinb + (size_t)s * HD + lane * 4;
    float4 c = *(const float4*)cp;
    float4 sn = *(const float4*)sp;

    float4 o;
    o.x = x0 * c.x + sgn * p0 * sn.x;
    o.y = x1 * c.y + sgn * p1 * sn.y;
    o.z = x2 * c.z + sgn * p2 * sn.z;
    o.w = x3 * c.w + sgn * p3 * sn.w;
    *(float4*)(x + lane * 4) = o;
}

// ---------------------------------------------------------------------------
// Flash attention, fp32, causal, GQA (head h -> kv head h/4).
// Br = Bc = 64, 256 threads. grid = (S/64 qblocks, NH heads).
// Dynamic smem: Qs[64][132] + Ks[64][132] + Vs[64][128] + Ps[64][65]
// ---------------------------------------------------------------------------
#define ATT_SMEM_FLOATS (64 * 132 + 64 * 132 + 64 * 128 + 64 * 65)

__global__ __launch_bounds__(256) void attn_kernel(
    const float* __restrict__ Q, const float* __restrict__ K,
    const float* __restrict__ V, float* __restrict__ O)
{
    extern __shared__ float sm[];
    float* Qs = sm;                        // [64][132]
    float* Ks = Qs + 64 * 132;             // [64][132]
    float* Vs = Ks + 64 * 132;             // [64][128]
    float* Ps = Vs + 64 * 128;             // [64][65]

    const int qb = blockIdx.x;
    const int h  = blockIdx.y;
    const int kvh = h >> 2;
    const int tid = threadIdx.x;
    const int tx = tid & 15;    // score cols / output d-cols
    const int ty = tid >> 4;    // q rows (4 per thread)
    const int q0 = qb * 64;

    // Load Q tile
    for (int i = tid; i < 64 * 32; i += 256) {
        int r = i >> 5;
        int c = (i & 31) << 2;
        *(float4*)&Qs[r * 132 + c] =
            *(const float4*)(Q + (size_t)(q0 + r) * QDIM + h * HD + c);
    }

    float accO[4][8];
    float m_i[4], l_i[4];
#pragma unroll
    for (int i = 0; i < 4; i++) {
        m_i[i] = -1e30f; l_i[i] = 0.0f;
#pragma unroll
        for (int j = 0; j < 8; j++) accO[i][j] = 0.0f;
    }
    __syncthreads();

    for (int jb = 0; jb <= qb; jb++) {
        const int k0 = jb * 64;
        // Load K, V tiles
        for (int i = tid; i < 64 * 32; i += 256) {
            int r = i >> 5;
            int c = (i & 31) << 2;
            size_t goff = (size_t)(k0 + r) * KVDIM + kvh * HD + c;
            *(float4*)&Ks[r * 132 + c] = *(const float4*)(K + goff);
            *(float4*)&Vs[r * 128 + c] = *(const float4*)(V + goff);
        }
        __syncthreads();

        // Scores: s[i][j] = Q[ty*4+i] . K[tx*4+j]
        float sc[4][4];
#pragma unroll
        for (int i = 0; i < 4; i++)
#pragma unroll
            for (int j = 0; j < 4; j++) sc[i][j] = 0.0f;

        for (int k = 0; k < HD; k += 4) {
            float4 qv[4], kv[4];
#pragma unroll
            for (int i = 0; i < 4; i++)
                qv[i] = *(const float4*)&Qs[(ty * 4 + i) * 132 + k];
#pragma unroll
            for (int j = 0; j < 4; j++)
                kv[j] = *(const float4*)&Ks[(tx * 4 + j) * 132 + k];
#pragma unroll
            for (int i = 0; i < 4; i++)
#pragma unroll
                for (int j = 0; j < 4; j++) {
                    sc[i][j] = fmaf(qv[i].x, kv[j].x, sc[i][j]);
                    sc[i][j] = fmaf(qv[i].y, kv[j].y, sc[i][j]);
                    sc[i][j] = fmaf(qv[i].z, kv[j].z, sc[i][j]);
                    sc[i][j] = fmaf(qv[i].w, kv[j].w, sc[i][j]);
                }
        }

        const bool diag = (jb == qb);
        float p[4][4], rm[4], rs[4];
#pragma unroll
        for (int i = 0; i < 4; i++) {
            rm[i] = -1e30f;
#pragma unroll
            for (int j = 0; j < 4; j++) {
                float v = sc[i][j] * RSCALE;
                if (diag && (tx * 4 + j) > (ty * 4 + i)) v = -1e30f;
                p[i][j] = v;
                rm[i] = fmaxf(rm[i], v);
            }
        }
        // reduce max over the 16 lanes owning this row group
#pragma unroll
        for (int i = 0; i < 4; i++) {
#pragma unroll
            for (int o = 8; o > 0; o >>= 1)
                rm[i] = fmaxf(rm[i], __shfl_xor_sync(0xffffffffu, rm[i], o));
        }
#pragma unroll
        for (int i = 0; i < 4; i++) {
            float m_new = fmaxf(m_i[i], rm[i]);
            float alpha = __expf(m_i[i] - m_new);
            rs[i] = 0.0f;
#pragma unroll
            for (int j = 0; j < 4; j++) {
                float pe = __expf(p[i][j] - m_new);
                p[i][j] = pe;
                rs[i] += pe;
            }
#pragma unroll
            for (int o = 8; o > 0; o >>= 1)
                rs[i] += __shfl_xor_sync(0xffffffffu, rs[i], o);
            l_i[i] = l_i[i] * alpha + rs[i];
            m_i[i] = m_new;
#pragma unroll
            for (int j = 0; j < 8; j++) accO[i][j] *= alpha;
        }
        // stage P
#pragma unroll
        for (int i = 0; i < 4; i++)
#pragma unroll
            for (int j = 0; j < 4; j++)
                Ps[(ty * 4 + i) * 65 + tx * 4 + j] = p[i][j];
        __syncthreads();

        // O += P @ V ;  thread owns rows ty*4+i, d-cols tx*8..tx*8+7
#pragma unroll 4
        for (int c = 0; c < 64; c++) {
            float pr[4];
#pragma unroll
            for (int i = 0; i < 4; i++) pr[i] = Ps[(ty * 4 + i) * 65 + c];
            float4 v0 = *(const float4*)&Vs[c * 128 + tx * 8];
            float4 v1 = *(const float4*)&Vs[c * 128 + tx * 8 + 4];
#pragma unroll
            for (int i = 0; i < 4; i++) {
                accO[i][0] = fmaf(pr[i], v0.x, accO[i][0]);
                accO[i][1] = fmaf(pr[i], v0.y, accO[i][1]);
                accO[i][2] = fmaf(pr[i], v0.z, accO[i][2]);
                accO[i][3] = fmaf(pr[i], v0.w, accO[i][3]);
                accO[i][4] = fmaf(pr[i], v1.x, accO[i][4]);
                accO[i][5] = fmaf(pr[i], v1.y, accO[i][5]);
                accO[i][6] = fmaf(pr[i], v1.z, accO[i][6]);
                accO[i][7] = fmaf(pr[i], v1.w, accO[i][7]);
            }
        }
        __syncthreads();   // protect Ks/Vs/Ps before next iteration
    }

    // Finalize
#pragma unroll
    for (int i = 0; i < 4; i++) {
        float inv = 1.0f / l_i[i];
        float* op = O + (size_t)(q0 + ty * 4 + i) * QDIM + h * HD + tx * 8;
        float4 o0 = make_float4(accO[i][0] * inv, accO[i][1] * inv,
                                accO[i][2] * inv, accO[i][3] * inv);
        float4 o1 = make_float4(accO[i][4] * inv, accO[i][5] * inv,
                                accO[i][6] * inv, accO[i][7] * inv);
        *(float4*)op = o0;
        *(float4*)(op + 4) = o1;
    }
}

// ---------------------------------------------------------------------------
extern "C" void kernel_launch(void* const* d_in, const int* in_sizes, int n_in,
                              void* d_out, int out_size)
{
    const float* hidden = (const float*)d_in[0];
    const float* cosb   = (const float*)d_in[1];
    const float* sinb   = (const float*)d_in[2];
    const float* Wq     = (const float*)d_in[3];
    const float* Wk     = (const float*)d_in[4];
    const float* Wv     = (const float*)d_in[5];
    const float* Wo     = (const float*)d_in[6];
    const float* qw     = (const float*)d_in[7];
    const float* kw     = (const float*)d_in[8];
    float* out = (float*)d_out;

    float *Qp, *Kp, *Vp, *AOp;
    cudaGetSymbolAddress((void**)&Qp,  g_Q);
    cudaGetSymbolAddress((void**)&Kp,  g_K);
    cudaGetSymbolAddress((void**)&Vp,  g_V);
    cudaGetSymbolAddress((void**)&AOp, g_AO);

    const int att_smem = ATT_SMEM_FLOATS * (int)sizeof(float);
    cudaFuncSetAttribute(attn_kernel,
                         cudaFuncAttributeMaxDynamicSharedMemorySize, att_smem);

    // Projections
    sgemm_nt<<<dim3(QDIM / 128, SEQ / 128), 256>>>(hidden, Wq, Qp, SEQ, QDIM, HID);
    sgemm_nt<<<dim3(KVDIM / 128, SEQ / 128), 256>>>(hidden, Wk, Kp, SEQ, KVDIM, HID);
    sgemm_nt<<<dim3(KVDIM / 128, SEQ / 128), 256>>>(hidden, Wv, Vp, SEQ, KVDIM, HID);

    // RMSNorm + RoPE (Q and K)
    rmsnorm_rope<<<(SEQ * NH) / 8, 256>>>(Qp, qw, cosb, sinb, NH);
    rmsnorm_rope<<<(SEQ * NKV) / 8, 256>>>(Kp, kw, cosb, sinb, NKV);

    // Attention
    attn_kernel<<<dim3(SEQ / 64, NH), 256, att_smem>>>(Qp, Kp, Vp, AOp);

    // Output projection
    sgemm_nt<<<dim3(HID / 128, SEQ / 128), 256>>>(AOp, Wo, out, SEQ, HID, QDIM);
}

// round 5
// speedup vs baseline: 1.6983x; 1.6983x over previous
#include <cuda_runtime.h>
#include <cuda_bf16.h>
#include <stdint.h>
#include <math.h>

// Problem constants (B=1)
#define SEQ   2048
#define HID   4096
#define NH    32
#define NKV   8
#define HD    128
#define QDIM  (NH * HD)   // 4096
#define KVDIM (NKV * HD)  // 1024
#define RSCALE 0.08838834764831845f  // 128^-0.5
#define REPS   1e-6f

// ---------------------------------------------------------------------------
// Scratch (__device__ globals: allocation-free rule)
// ---------------------------------------------------------------------------
__device__ float g_Q[SEQ * QDIM];
__device__ float g_K[SEQ * KVDIM];
__device__ float g_V[SEQ * KVDIM];
__device__ float g_AO[SEQ * QDIM];

__device__ __nv_bfloat16 g_Xhi[SEQ * HID],    g_Xlo[SEQ * HID];
__device__ __nv_bfloat16 g_Wqh[QDIM * HID],   g_Wql[QDIM * HID];
__device__ __nv_bfloat16 g_Wkh[KVDIM * HID],  g_Wkl[KVDIM * HID];
__device__ __nv_bfloat16 g_Wvh[KVDIM * HID],  g_Wvl[KVDIM * HID];
__device__ __nv_bfloat16 g_Woh[HID * QDIM],   g_Wol[HID * QDIM];
__device__ __nv_bfloat16 g_AOh[SEQ * QDIM],   g_AOl[SEQ * QDIM];

// ---------------------------------------------------------------------------
// PTX helpers (base sm_100-safe: mma.sync / ldmatrix / cp.async only)
// ---------------------------------------------------------------------------
__device__ __forceinline__ uint32_t smem_u32(const void* p) {
    uint32_t a;
    asm("{ .reg .u64 t; cvta.to.shared.u64 t, %1; cvt.u32.u64 %0, t; }"
        : "=r"(a) : "l"(p));
    return a;
}

__device__ __forceinline__ void ldsm4(uint32_t* r, uint32_t addr) {
    asm volatile("ldmatrix.sync.aligned.m8n8.x4.shared.b16 {%0,%1,%2,%3}, [%4];"
                 : "=r"(r[0]), "=r"(r[1]), "=r"(r[2]), "=r"(r[3]) : "r"(addr));
}

__device__ __forceinline__ void mma16816(float* c, const uint32_t* a,
                                         uint32_t b0, uint32_t b1) {
    asm volatile(
        "mma.sync.aligned.m16n8k16.row.col.f32.bf16.bf16.f32 "
        "{%0,%1,%2,%3}, {%4,%5,%6,%7}, {%8,%9}, {%0,%1,%2,%3};"
        : "+f"(c[0]), "+f"(c[1]), "+f"(c[2]), "+f"(c[3])
        : "r"(a[0]), "r"(a[1]), "r"(a[2]), "r"(a[3]), "r"(b0), "r"(b1));
}

// ---------------------------------------------------------------------------
// fp32 -> (bf16 hi, bf16 lo) split conversion
// ---------------------------------------------------------------------------
__global__ __launch_bounds__(256) void cvt_split(
    const float* __restrict__ x, __nv_bfloat16* __restrict__ hi,
    __nv_bfloat16* __restrict__ lo, int n)
{
    int i = (blockIdx.x * 256 + threadIdx.x) * 4;
    if (i >= n) return;
    float4 v = *(const float4*)(x + i);
    __nv_bfloat16 h0 = __float2bfloat16(v.x);
    __nv_bfloat16 h1 = __float2bfloat16(v.y);
    __nv_bfloat16 h2 = __float2bfloat16(v.z);
    __nv_bfloat16 h3 = __float2bfloat16(v.w);
    __nv_bfloat16 l0 = __float2bfloat16(v.x - __bfloat162float(h0));
    __nv_bfloat16 l1 = __float2bfloat16(v.y - __bfloat162float(h1));
    __nv_bfloat16 l2 = __float2bfloat16(v.z - __bfloat162float(h2));
    __nv_bfloat16 l3 = __float2bfloat16(v.w - __bfloat162float(h3));
    *(__nv_bfloat162*)(hi + i)     = __nv_bfloat162(h0, h1);
    *(__nv_bfloat162*)(hi + i + 2) = __nv_bfloat162(h2, h3);
    *(__nv_bfloat162*)(lo + i)     = __nv_bfloat162(l0, l1);
    *(__nv_bfloat162*)(lo + i + 2) = __nv_bfloat162(l2, l3);
}

// ---------------------------------------------------------------------------
// mma.sync bf16x3 GEMM: C[M,N] = (Ahi+Alo)[M,K] * (Bhi+Blo)[N,K]^T  (fp32 out)
// 128x128 CTA tile, BK=64, 256 threads (8 warps, 64x32 warp tile).
// Double-buffered cp.async; smem rows are 128B with XOR-8 swizzle.
// ---------------------------------------------------------------------------
#define TILE_B   16384                  // 128 rows x 128 bytes (one component)
#define STAGE_B  (4 * TILE_B)           // Ahi, Alo, Bhi, Blo
#define GSM_TOTAL (2 * STAGE_B)         // 131072 bytes

__device__ __forceinline__ void load_tile64(
    uint32_t sdst, const __nv_bfloat16* __restrict__ g,
    int row0, int kc, int K, int tid)
{
#pragma unroll
    for (int s = 0; s < 4; s++) {
        int idx = tid + s * 256;           // 0..1023
        int r = idx >> 3;                  // 0..127
        int u = idx & 7;                   // 16B unit within 128B row
        uint32_t sw = (uint32_t)(r * 128 + ((u ^ (r & 7)) << 4));
        const __nv_bfloat16* gp = g + (size_t)(row0 + r) * K + kc * 64 + u * 8;
        asm volatile("cp.async.cg.shared.global [%0], [%1], 16;"
                     :: "r"(sdst + sw), "l"(gp) : "memory");
    }
}

__global__ __launch_bounds__(256)
void gemm_bf16x3(
    const __nv_bfloat16* __restrict__ Ahi, const __nv_bfloat16* __restrict__ Alo,
    const __nv_bfloat16* __restrict__ Bhi, const __nv_bfloat16* __restrict__ Blo,
    float* __restrict__ C, int M, int N, int K)
{
    extern __shared__ __align__(1024) char smem[];
    const uint32_t sb = smem_u32(smem);
    const int tid  = threadIdx.x;
    const int lane = tid & 31;
    const int warp = tid >> 5;
    const int wm = warp >> 2;     // 0..1  -> m offset wm*64
    const int wn = warp & 3;      // 0..3  -> n offset wn*32
    const int bm = blockIdx.y * 128;
    const int bn = blockIdx.x * 128;
    const int NC = K >> 6;

    float acc[4][4][4];
#pragma unroll
    for (int i = 0; i < 4; i++)
#pragma unroll
        for (int j = 0; j < 4; j++)
#pragma unroll
            for (int q = 0; q < 4; q++) acc[i][j][q] = 0.0f;

    // Prologue: stages 0 and 1
#pragma unroll
    for (int c = 0; c < 2; c++) {
        uint32_t b = sb + c * STAGE_B;
        load_tile64(b,              Ahi, bm, c, K, tid);
        load_tile64(b + TILE_B,     Alo, bm, c, K, tid);
        load_tile64(b + 2 * TILE_B, Bhi, bn, c, K, tid);
        load_tile64(b + 3 * TILE_B, Blo, bn, c, K, tid);
        asm volatile("cp.async.commit_group;" ::: "memory");
    }

    // Per-lane ldmatrix source rows (within warp tile)
    const int a_r  = wm * 64 + (lane & 15);           // + mt*16
    const int a_ku = lane >> 4;                       // + k0/8
    const int b_r  = wn * 32 + ((lane >> 3) & 1) * 8 + (lane & 7);  // + ntp*16
    const int b_ku = lane >> 4;                       // + k0/8

    for (int c = 0; c < NC; c++) {
        const uint32_t b = sb + (c & 1) * STAGE_B;
        if (c + 1 < NC)
            asm volatile("cp.async.wait_group 1;" ::: "memory");
        else
            asm volatile("cp.async.wait_group 0;" ::: "memory");
        __syncthreads();

        const uint32_t sAh = b;
        const uint32_t sAl = b + TILE_B;
        const uint32_t sBh = b + 2 * TILE_B;
        const uint32_t sBl = b + 3 * TILE_B;

#pragma unroll
        for (int ks = 0; ks < 4; ks++) {
            const int ku0 = ks * 2;
            uint32_t aH[4][4], aL[4][4];
#pragma unroll
            for (int mt = 0; mt < 4; mt++) {
                int r = a_r + mt * 16;
                int ku = ku0 + a_ku;
                uint32_t off = (uint32_t)(r * 128 + ((ku ^ (r & 7)) << 4));
                ldsm4(aH[mt], sAh + off);
                ldsm4(aL[mt], sAl + off);
            }
            uint32_t bH[2][4], bL[2][4];
#pragma unroll
            for (int ntp = 0; ntp < 2; ntp++) {
                int r = b_r + ntp * 16;
                int ku = ku0 + b_ku;
                uint32_t off = (uint32_t)(r * 128 + ((ku ^ (r & 7)) << 4));
                ldsm4(bH[ntp], sBh + off);
                ldsm4(bL[ntp], sBl + off);
            }
#pragma unroll
            for (int mt = 0; mt < 4; mt++) {
#pragma unroll
                for (int nt = 0; nt < 4; nt++) {
                    const int ntp = nt >> 1;
                    const int sel = nt & 1;
                    mma16816(acc[mt][nt], aH[mt], bH[ntp][sel], bH[ntp][sel + 2]);
                    mma16816(acc[mt][nt], aH[mt], bL[ntp][sel], bL[ntp][sel + 2]);
                    mma16816(acc[mt][nt], aL[mt], bH[ntp][sel], bH[ntp][sel + 2]);
                }
            }
        }
        __syncthreads();

        if (c + 2 < NC) {
            load_tile64(b,              Ahi, bm, c + 2, K, tid);
            load_tile64(b + TILE_B,     Alo, bm, c + 2, K, tid);
            load_tile64(b + 2 * TILE_B, Bhi, bn, c + 2, K, tid);
            load_tile64(b + 3 * TILE_B, Blo, bn, c + 2, K, tid);
            asm volatile("cp.async.commit_group;" ::: "memory");
        }
    }

    // Epilogue: fragment rows -> C
#pragma unroll
    for (int mt = 0; mt < 4; mt++) {
        const int row = bm + wm * 64 + mt * 16 + (lane >> 2);
#pragma unroll
        for (int nt = 0; nt < 4; nt++) {
            const int col = bn + wn * 32 + nt * 8 + (lane & 3) * 2;
            *(float2*)(C + (size_t)row * N + col) =
                make_float2(acc[mt][nt][0], acc[mt][nt][1]);
            *(float2*)(C + (size_t)(row + 8) * N + col) =
                make_float2(acc[mt][nt][2], acc[mt][nt][3]);
        }
    }
}

// ---------------------------------------------------------------------------
// Fused RMSNorm + RoPE (unchanged)
// ---------------------------------------------------------------------------
__global__ __launch_bounds__(256) void rmsnorm_rope(
    float* __restrict__ X, const float* __restrict__ w,
    const float* __restrict__ cosb, const float* __restrict__ sinb,
    int nheads)
{
    const int row  = blockIdx.x * 8 + (threadIdx.x >> 5);
    const int lane = threadIdx.x & 31;
    const int s    = row / nheads;

    float* x = X + (size_t)row * HD;
    float4 v = *(const float4*)(x + lane * 4);

    float ss = v.x * v.x + v.y * v.y + v.z * v.z + v.w * v.w;
#pragma unroll
    for (int o = 16; o > 0; o >>= 1) ss += __shfl_xor_sync(0xffffffffu, ss, o);
    const float inv = rsqrtf(ss * (1.0f / 128.0f) + REPS);

    float4 wv = *(const float4*)(w + lane * 4);
    float x0 = v.x * inv * wv.x;
    float x1 = v.y * inv * wv.y;
    float x2 = v.z * inv * wv.z;
    float x3 = v.w * inv * wv.w;

    float p0 = __shfl_xor_sync(0xffffffffu, x0, 16);
    float p1 = __shfl_xor_sync(0xffffffffu, x1, 16);
    float p2 = __shfl_xor_sync(0xffffffffu, x2, 16);
    float p3 = __shfl_xor_sync(0xffffffffu, x3, 16);
    const float sgn = (lane < 16) ? -1.0f : 1.0f;

    const float* cp = cosb + (size_t)s * HD + lane * 4;
    const float* sp = sinb + (size_t)s * HD + lane * 4;
    float4 c = *(const float4*)cp;
    float4 sn = *(const float4*)sp;

    float4 o;
    o.x = x0 * c.x + sgn * p0 * sn.x;
    o.y = x1 * c.y + sgn * p1 * sn.y;
    o.z = x2 * c.z + sgn * p2 * sn.z;
    o.w = x3 * c.w + sgn * p3 * sn.w;
    *(float4*)(x + lane * 4) = o;
}

// ---------------------------------------------------------------------------
// Flash attention fp32 (unchanged)
// ---------------------------------------------------------------------------
#define ATT_SMEM_FLOATS (64 * 132 + 64 * 132 + 64 * 128 + 64 * 65)

__global__ __launch_bounds__(256) void attn_kernel(
    const float* __restrict__ Q, const float* __restrict__ K,
    const float* __restrict__ V, float* __restrict__ O)
{
    extern __shared__ float sm[];
    float* Qs = sm;
    float* Ks = Qs + 64 * 132;
    float* Vs = Ks + 64 * 132;
    float* Ps = Vs + 64 * 128;

    const int qb = blockIdx.x;
    const int h  = blockIdx.y;
    const int kvh = h >> 2;
    const int tid = threadIdx.x;
    const int tx = tid & 15;
    const int ty = tid >> 4;
    const int q0 = qb * 64;

    for (int i = tid; i < 64 * 32; i += 256) {
        int r = i >> 5;
        int c = (i & 31) << 2;
        *(float4*)&Qs[r * 132 + c] =
            *(const float4*)(Q + (size_t)(q0 + r) * QDIM + h * HD + c);
    }

    float accO[4][8];
    float m_i[4], l_i[4];
#pragma unroll
    for (int i = 0; i < 4; i++) {
        m_i[i] = -1e30f; l_i[i] = 0.0f;
#pragma unroll
        for (int j = 0; j < 8; j++) accO[i][j] = 0.0f;
    }
    __syncthreads();

    for (int jb = 0; jb <= qb; jb++) {
        const int k0 = jb * 64;
        for (int i = tid; i < 64 * 32; i += 256) {
            int r = i >> 5;
            int c = (i & 31) << 2;
            size_t goff = (size_t)(k0 + r) * KVDIM + kvh * HD + c;
            *(float4*)&Ks[r * 132 + c] = *(const float4*)(K + goff);
            *(float4*)&Vs[r * 128 + c] = *(const float4*)(V + goff);
        }
        __syncthreads();

        float sc[4][4];
#pragma unroll
        for (int i = 0; i < 4; i++)
#pragma unroll
            for (int j = 0; j < 4; j++) sc[i][j] = 0.0f;

        for (int k = 0; k < HD; k += 4) {
            float4 qv[4], kv[4];
#pragma unroll
            for (int i = 0; i < 4; i++)
                qv[i] = *(const float4*)&Qs[(ty * 4 + i) * 132 + k];
#pragma unroll
            for (int j = 0; j < 4; j++)
                kv[j] = *(const float4*)&Ks[(tx * 4 + j) * 132 + k];
#pragma unroll
            for (int i = 0; i < 4; i++)
#pragma unroll
                for (int j = 0; j < 4; j++) {
                    sc[i][j] = fmaf(qv[i].x, kv[j].x, sc[i][j]);
                    sc[i][j] = fmaf(qv[i].y, kv[j].y, sc[i][j]);
                    sc[i][j] = fmaf(qv[i].z, kv[j].z, sc[i][j]);
                    sc[i][j] = fmaf(qv[i].w, kv[j].w, sc[i][j]);
                }
        }

        const bool diag = (jb == qb);
        float p[4][4], rm[4], rs[4];
#pragma unroll
        for (int i = 0; i < 4; i++) {
            rm[i] = -1e30f;
#pragma unroll
            for (int j = 0; j < 4; j++) {
                float v = sc[i][j] * RSCALE;
                if (diag && (tx * 4 + j) > (ty * 4 + i)) v = -1e30f;
                p[i][j] = v;
                rm[i] = fmaxf(rm[i], v);
            }
        }
#pragma unroll
        for (int i = 0; i < 4; i++) {
#pragma unroll
            for (int o = 8; o > 0; o >>= 1)
                rm[i] = fmaxf(rm[i], __shfl_xor_sync(0xffffffffu, rm[i], o));
        }
#pragma unroll
        for (int i = 0; i < 4; i++) {
            float m_new = fmaxf(m_i[i], rm[i]);
            float alpha = __expf(m_i[i] - m_new);
            rs[i] = 0.0f;
#pragma unroll
            for (int j = 0; j < 4; j++) {
                float pe = __expf(p[i][j] - m_new);
                p[i][j] = pe;
                rs[i] += pe;
            }
#pragma unroll
            for (int o = 8; o > 0; o >>= 1)
                rs[i] += __shfl_xor_sync(0xffffffffu, rs[i], o);
            l_i[i] = l_i[i] * alpha + rs[i];
            m_i[i] = m_new;
#pragma unroll
            for (int j = 0; j < 8; j++) accO[i][j] *= alpha;
        }
#pragma unroll
        for (int i = 0; i < 4; i++)
#pragma unroll
            for (int j = 0; j < 4; j++)
                Ps[(ty * 4 + i) * 65 + tx * 4 + j] = p[i][j];
        __syncthreads();

#pragma unroll 4
        for (int c = 0; c < 64; c++) {
            float pr[4];
#pragma unroll
            for (int i = 0; i < 4; i++) pr[i] = Ps[(ty * 4 + i) * 65 + c];
            float4 v0 = *(const float4*)&Vs[c * 128 + tx * 8];
            float4 v1 = *(const float4*)&Vs[c * 128 + tx * 8 + 4];
#pragma unroll
            for (int i = 0; i < 4; i++) {
                accO[i][0] = fmaf(pr[i], v0.x, accO[i][0]);
                accO[i][1] = fmaf(pr[i], v0.y, accO[i][1]);
                accO[i][2] = fmaf(pr[i], v0.z, accO[i][2]);
                accO[i][3] = fmaf(pr[i], v0.w, accO[i][3]);
                accO[i][4] = fmaf(pr[i], v1.x, accO[i][4]);
                accO[i][5] = fmaf(pr[i], v1.y, accO[i][5]);
                accO[i][6] = fmaf(pr[i], v1.z, accO[i][6]);
                accO[i][7] = fmaf(pr[i], v1.w, accO[i][7]);
            }
        }
        __syncthreads();
    }

#pragma unroll
    for (int i = 0; i < 4; i++) {
        float inv = 1.0f / l_i[i];
        float* op = O + (size_t)(q0 + ty * 4 + i) * QDIM + h * HD + tx * 8;
        float4 o0 = make_float4(accO[i][0] * inv, accO[i][1] * inv,
                                accO[i][2] * inv, accO[i][3] * inv);
        float4 o1 = make_float4(accO[i][4] * inv, accO[i][5] * inv,
                                accO[i][6] * inv, accO[i][7] * inv);
        *(float4*)op = o0;
        *(float4*)(op + 4) = o1;
    }
}

// ---------------------------------------------------------------------------
extern "C" void kernel_launch(void* const* d_in, const int* in_sizes, int n_in,
                              void* d_out, int out_size)
{
    const float* hidden = (const float*)d_in[0];
    const float* cosb   = (const float*)d_in[1];
    const float* sinb   = (const float*)d_in[2];
    const float* Wq     = (const float*)d_in[3];
    const float* Wk     = (const float*)d_in[4];
    const float* Wv     = (const float*)d_in[5];
    const float* Wo     = (const float*)d_in[6];
    const float* qw     = (const float*)d_in[7];
    const float* kw     = (const float*)d_in[8];
    float* out = (float*)d_out;

    float *Qp, *Kp, *Vp, *AOp;
    cudaGetSymbolAddress((void**)&Qp,  g_Q);
    cudaGetSymbolAddress((void**)&Kp,  g_K);
    cudaGetSymbolAddress((void**)&Vp,  g_V);
    cudaGetSymbolAddress((void**)&AOp, g_AO);

    __nv_bfloat16 *Xh, *Xl, *Wqh, *Wql, *Wkh, *Wkl, *Wvh, *Wvl, *Woh, *Wol, *AOh, *AOl;
    cudaGetSymbolAddress((void**)&Xh,  g_Xhi);  cudaGetSymbolAddress((void**)&Xl,  g_Xlo);
    cudaGetSymbolAddress((void**)&Wqh, g_Wqh);  cudaGetSymbolAddress((void**)&Wql, g_Wql);
    cudaGetSymbolAddress((void**)&Wkh, g_Wkh);  cudaGetSymbolAddress((void**)&Wkl, g_Wkl);
    cudaGetSymbolAddress((void**)&Wvh, g_Wvh);  cudaGetSymbolAddress((void**)&Wvl, g_Wvl);
    cudaGetSymbolAddress((void**)&Woh, g_Woh);  cudaGetSymbolAddress((void**)&Wol, g_Wol);
    cudaGetSymbolAddress((void**)&AOh, g_AOh);  cudaGetSymbolAddress((void**)&AOl, g_AOl);

    const int att_smem = ATT_SMEM_FLOATS * (int)sizeof(float);
    cudaFuncSetAttribute(attn_kernel,
                         cudaFuncAttributeMaxDynamicSharedMemorySize, att_smem);
    cudaFuncSetAttribute(gemm_bf16x3,
                         cudaFuncAttributeMaxDynamicSharedMemorySize, GSM_TOTAL);

    // Split conversions
    cvt_split<<<(SEQ * HID) / 1024, 256>>>(hidden, Xh, Xl, SEQ * HID);
    cvt_split<<<(QDIM * HID) / 1024, 256>>>(Wq, Wqh, Wql, QDIM * HID);
    cvt_split<<<(KVDIM * HID) / 1024, 256>>>(Wk, Wkh, Wkl, KVDIM * HID);
    cvt_split<<<(KVDIM * HID) / 1024, 256>>>(Wv, Wvh, Wvl, KVDIM * HID);
    cvt_split<<<(HID * QDIM) / 1024, 256>>>(Wo, Woh, Wol, HID * QDIM);

    // Projections (tensor cores, bf16x3)
    gemm_bf16x3<<<dim3(QDIM / 128, SEQ / 128), 256, GSM_TOTAL>>>(
        Xh, Xl, Wqh, Wql, Qp, SEQ, QDIM, HID);
    gemm_bf16x3<<<dim3(KVDIM / 128, SEQ / 128), 256, GSM_TOTAL>>>(
        Xh, Xl, Wkh, Wkl, Kp, SEQ, KVDIM, HID);
    gemm_bf16x3<<<dim3(KVDIM / 128, SEQ / 128), 256, GSM_TOTAL>>>(
        Xh, Xl, Wvh, Wvl, Vp, SEQ, KVDIM, HID);

    // RMSNorm + RoPE
    rmsnorm_rope<<<(SEQ * NH) / 8, 256>>>(Qp, qw, cosb, sinb, NH);
    rmsnorm_rope<<<(SEQ * NKV) / 8, 256>>>(Kp, kw, cosb, sinb, NKV);

    // Attention (fp32)
    attn_kernel<<<dim3(SEQ / 64, NH), 256, att_smem>>>(Qp, Kp, Vp, AOp);

    // Output projection
    cvt_split<<<(SEQ * QDIM) / 1024, 256>>>(AOp, AOh, AOl, SEQ * QDIM);
    gemm_bf16x3<<<dim3(HID / 128, SEQ / 128), 256, GSM_TOTAL>>>(
        AOh, AOl, Woh, Wol, out, SEQ, HID, QDIM);
}

// round 6
// speedup vs baseline: 3.0727x; 1.8093x over previous
#include <cuda_runtime.h>
#include <cuda_bf16.h>
#include <stdint.h>
#include <math.h>

// Problem constants (B=1)
#define SEQ   2048
#define HID   4096
#define NH    32
#define NKV   8
#define HD    128
#define QDIM  (NH * HD)   // 4096
#define KVDIM (NKV * HD)  // 1024
#define RSCALE 0.08838834764831845f  // 128^-0.5
#define REPS   1e-6f

// ---------------------------------------------------------------------------
// Scratch (__device__ globals: allocation-free rule)
// ---------------------------------------------------------------------------
__device__ float g_Q[SEQ * QDIM];
__device__ float g_K[SEQ * KVDIM];
__device__ float g_V[SEQ * KVDIM];
__device__ float g_AO[SEQ * QDIM];

__device__ __nv_bfloat16 g_Xhi[SEQ * HID],    g_Xlo[SEQ * HID];
__device__ __nv_bfloat16 g_Wqh[QDIM * HID],   g_Wql[QDIM * HID];
__device__ __nv_bfloat16 g_Wkh[KVDIM * HID],  g_Wkl[KVDIM * HID];
__device__ __nv_bfloat16 g_Wvh[KVDIM * HID],  g_Wvl[KVDIM * HID];
__device__ __nv_bfloat16 g_Woh[HID * QDIM],   g_Wol[HID * QDIM];
__device__ __nv_bfloat16 g_AOh[SEQ * QDIM],   g_AOl[SEQ * QDIM];

__device__ __nv_bfloat16 g_Qh2[SEQ * QDIM],   g_Ql2[SEQ * QDIM];
__device__ __nv_bfloat16 g_Kh2[SEQ * KVDIM],  g_Kl2[SEQ * KVDIM];
__device__ __nv_bfloat16 g_Vh2[SEQ * KVDIM],  g_Vl2[SEQ * KVDIM];

// ---------------------------------------------------------------------------
// PTX helpers (base sm_100-safe)
// ---------------------------------------------------------------------------
__device__ __forceinline__ uint32_t smem_u32(const void* p) {
    uint32_t a;
    asm("{ .reg .u64 t; cvta.to.shared.u64 t, %1; cvt.u32.u64 %0, t; }"
        : "=r"(a) : "l"(p));
    return a;
}

__device__ __forceinline__ void ldsm4(uint32_t* r, uint32_t addr) {
    asm volatile("ldmatrix.sync.aligned.m8n8.x4.shared.b16 {%0,%1,%2,%3}, [%4];"
                 : "=r"(r[0]), "=r"(r[1]), "=r"(r[2]), "=r"(r[3]) : "r"(addr));
}

__device__ __forceinline__ void ldsm4t(uint32_t* r, uint32_t addr) {
    asm volatile("ldmatrix.sync.aligned.m8n8.x4.trans.shared.b16 {%0,%1,%2,%3}, [%4];"
                 : "=r"(r[0]), "=r"(r[1]), "=r"(r[2]), "=r"(r[3]) : "r"(addr));
}

__device__ __forceinline__ void mma16816(float* c, const uint32_t* a,
                                         uint32_t b0, uint32_t b1) {
    asm volatile(
        "mma.sync.aligned.m16n8k16.row.col.f32.bf16.bf16.f32 "
        "{%0,%1,%2,%3}, {%4,%5,%6,%7}, {%8,%9}, {%0,%1,%2,%3};"
        : "+f"(c[0]), "+f"(c[1]), "+f"(c[2]), "+f"(c[3])
        : "r"(a[0]), "r"(a[1]), "r"(a[2]), "r"(a[3]), "r"(b0), "r"(b1));
}

__device__ __forceinline__ uint32_t pack_bf16(float lo, float hi) {
    __nv_bfloat162 t;
    t.x = __float2bfloat16(lo);
    t.y = __float2bfloat16(hi);
    return *(uint32_t*)&t;
}

// ---------------------------------------------------------------------------
// fp32 -> (bf16 hi, bf16 lo) split conversion
// ---------------------------------------------------------------------------
__global__ __launch_bounds__(256) void cvt_split(
    const float* __restrict__ x, __nv_bfloat16* __restrict__ hi,
    __nv_bfloat16* __restrict__ lo, int n)
{
    int i = (blockIdx.x * 256 + threadIdx.x) * 4;
    if (i >= n) return;
    float4 v = *(const float4*)(x + i);
    __nv_bfloat16 h0 = __float2bfloat16(v.x);
    __nv_bfloat16 h1 = __float2bfloat16(v.y);
    __nv_bfloat16 h2 = __float2bfloat16(v.z);
    __nv_bfloat16 h3 = __float2bfloat16(v.w);
    __nv_bfloat16 l0 = __float2bfloat16(v.x - __bfloat162float(h0));
    __nv_bfloat16 l1 = __float2bfloat16(v.y - __bfloat162float(h1));
    __nv_bfloat16 l2 = __float2bfloat16(v.z - __bfloat162float(h2));
    __nv_bfloat16 l3 = __float2bfloat16(v.w - __bfloat162float(h3));
    *(__nv_bfloat162*)(hi + i)     = __nv_bfloat162(h0, h1);
    *(__nv_bfloat162*)(hi + i + 2) = __nv_bfloat162(h2, h3);
    *(__nv_bfloat162*)(lo + i)     = __nv_bfloat162(l0, l1);
    *(__nv_bfloat162*)(lo + i + 2) = __nv_bfloat162(l2, l3);
}

// ---------------------------------------------------------------------------
// mma.sync bf16x3 GEMM (unchanged from R4)
// ---------------------------------------------------------------------------
#define TILE_B   16384
#define STAGE_B  (4 * TILE_B)
#define GSM_TOTAL (2 * STAGE_B)

__device__ __forceinline__ void load_tile64(
    uint32_t sdst, const __nv_bfloat16* __restrict__ g,
    int row0, int kc, int K, int tid)
{
#pragma unroll
    for (int s = 0; s < 4; s++) {
        int idx = tid + s * 256;
        int r = idx >> 3;
        int u = idx & 7;
        uint32_t sw = (uint32_t)(r * 128 + ((u ^ (r & 7)) << 4));
        const __nv_bfloat16* gp = g + (size_t)(row0 + r) * K + kc * 64 + u * 8;
        asm volatile("cp.async.cg.shared.global [%0], [%1], 16;"
                     :: "r"(sdst + sw), "l"(gp) : "memory");
    }
}

__global__ __launch_bounds__(256)
void gemm_bf16x3(
    const __nv_bfloat16* __restrict__ Ahi, const __nv_bfloat16* __restrict__ Alo,
    const __nv_bfloat16* __restrict__ Bhi, const __nv_bfloat16* __restrict__ Blo,
    float* __restrict__ C, int M, int N, int K)
{
    extern __shared__ __align__(1024) char smem[];
    const uint32_t sb = smem_u32(smem);
    const int tid  = threadIdx.x;
    const int lane = tid & 31;
    const int warp = tid >> 5;
    const int wm = warp >> 2;
    const int wn = warp & 3;
    const int bm = blockIdx.y * 128;
    const int bn = blockIdx.x * 128;
    const int NC = K >> 6;

    float acc[4][4][4];
#pragma unroll
    for (int i = 0; i < 4; i++)
#pragma unroll
        for (int j = 0; j < 4; j++)
#pragma unroll
            for (int q = 0; q < 4; q++) acc[i][j][q] = 0.0f;

#pragma unroll
    for (int c = 0; c < 2; c++) {
        uint32_t b = sb + c * STAGE_B;
        load_tile64(b,              Ahi, bm, c, K, tid);
        load_tile64(b + TILE_B,     Alo, bm, c, K, tid);
        load_tile64(b + 2 * TILE_B, Bhi, bn, c, K, tid);
        load_tile64(b + 3 * TILE_B, Blo, bn, c, K, tid);
        asm volatile("cp.async.commit_group;" ::: "memory");
    }

    const int a_r  = wm * 64 + (lane & 15);
    const int a_ku = lane >> 4;
    const int b_r  = wn * 32 + ((lane >> 3) & 1) * 8 + (lane & 7);
    const int b_ku = lane >> 4;

    for (int c = 0; c < NC; c++) {
        const uint32_t b = sb + (c & 1) * STAGE_B;
        if (c + 1 < NC)
            asm volatile("cp.async.wait_group 1;" ::: "memory");
        else
            asm volatile("cp.async.wait_group 0;" ::: "memory");
        __syncthreads();

        const uint32_t sAh = b;
        const uint32_t sAl = b + TILE_B;
        const uint32_t sBh = b + 2 * TILE_B;
        const uint32_t sBl = b + 3 * TILE_B;

#pragma unroll
        for (int ks = 0; ks < 4; ks++) {
            const int ku0 = ks * 2;
            uint32_t aH[4][4], aL[4][4];
#pragma unroll
            for (int mt = 0; mt < 4; mt++) {
                int r = a_r + mt * 16;
                int ku = ku0 + a_ku;
                uint32_t off = (uint32_t)(r * 128 + ((ku ^ (r & 7)) << 4));
                ldsm4(aH[mt], sAh + off);
                ldsm4(aL[mt], sAl + off);
            }
            uint32_t bH[2][4], bL[2][4];
#pragma unroll
            for (int ntp = 0; ntp < 2; ntp++) {
                int r = b_r + ntp * 16;
                int ku = ku0 + b_ku;
                uint32_t off = (uint32_t)(r * 128 + ((ku ^ (r & 7)) << 4));
                ldsm4(bH[ntp], sBh + off);
                ldsm4(bL[ntp], sBl + off);
            }
#pragma unroll
            for (int mt = 0; mt < 4; mt++) {
#pragma unroll
                for (int nt = 0; nt < 4; nt++) {
                    const int ntp = nt >> 1;
                    const int sel = nt & 1;
                    mma16816(acc[mt][nt], aH[mt], bH[ntp][sel], bH[ntp][sel + 2]);
                    mma16816(acc[mt][nt], aH[mt], bL[ntp][sel], bL[ntp][sel + 2]);
                    mma16816(acc[mt][nt], aL[mt], bH[ntp][sel], bH[ntp][sel + 2]);
                }
            }
        }
        __syncthreads();

        if (c + 2 < NC) {
            load_tile64(b,              Ahi, bm, c + 2, K, tid);
            load_tile64(b + TILE_B,     Alo, bm, c + 2, K, tid);
            load_tile64(b + 2 * TILE_B, Bhi, bn, c + 2, K, tid);
            load_tile64(b + 3 * TILE_B, Blo, bn, c + 2, K, tid);
            asm volatile("cp.async.commit_group;" ::: "memory");
        }
    }

#pragma unroll
    for (int mt = 0; mt < 4; mt++) {
        const int row = bm + wm * 64 + mt * 16 + (lane >> 2);
#pragma unroll
        for (int nt = 0; nt < 4; nt++) {
            const int col = bn + wn * 32 + nt * 8 + (lane & 3) * 2;
            *(float2*)(C + (size_t)row * N + col) =
                make_float2(acc[mt][nt][0], acc[mt][nt][1]);
            *(float2*)(C + (size_t)(row + 8) * N + col) =
                make_float2(acc[mt][nt][2], acc[mt][nt][3]);
        }
    }
}

// ---------------------------------------------------------------------------
// Fused RMSNorm + RoPE, writing bf16 hi/lo split directly
// ---------------------------------------------------------------------------
__global__ __launch_bounds__(256) void rmsnorm_rope_split(
    const float* __restrict__ X, const float* __restrict__ w,
    const float* __restrict__ cosb, const float* __restrict__ sinb,
    int nheads, __nv_bfloat16* __restrict__ oh, __nv_bfloat16* __restrict__ ol)
{
    const int row  = blockIdx.x * 8 + (threadIdx.x >> 5);
    const int lane = threadIdx.x & 31;
    const int s    = row / nheads;

    const float* x = X + (size_t)row * HD;
    float4 v = *(const float4*)(x + lane * 4);

    float ss = v.x * v.x + v.y * v.y + v.z * v.z + v.w * v.w;
#pragma unroll
    for (int o = 16; o > 0; o >>= 1) ss += __shfl_xor_sync(0xffffffffu, ss, o);
    const float inv = rsqrtf(ss * (1.0f / 128.0f) + REPS);

    float4 wv = *(const float4*)(w + lane * 4);
    float x0 = v.x * inv * wv.x;
    float x1 = v.y * inv * wv.y;
    float x2 = v.z * inv * wv.z;
    float x3 = v.w * inv * wv.w;

    float p0 = __shfl_xor_sync(0xffffffffu, x0, 16);
    float p1 = __shfl_xor_sync(0xffffffffu, x1, 16);
    float p2 = __shfl_xor_sync(0xffffffffu, x2, 16);
    float p3 = __shfl_xor_sync(0xffffffffu, x3, 16);
    const float sgn = (lane < 16) ? -1.0f : 1.0f;

    const float* cp = cosb + (size_t)s * HD + lane * 4;
    const float* sp = sinb + (size_t)s * HD + lane * 4;
    float4 c = *(const float4*)cp;
    float4 sn = *(const float4*)sp;

    float o0 = x0 * c.x + sgn * p0 * sn.x;
    float o1 = x1 * c.y + sgn * p1 * sn.y;
    float o2 = x2 * c.z + sgn * p2 * sn.z;
    float o3 = x3 * c.w + sgn * p3 * sn.w;

    __nv_bfloat16 h0 = __float2bfloat16(o0), h1 = __float2bfloat16(o1);
    __nv_bfloat16 h2 = __float2bfloat16(o2), h3 = __float2bfloat16(o3);
    __nv_bfloat16 l0 = __float2bfloat16(o0 - __bfloat162float(h0));
    __nv_bfloat16 l1 = __float2bfloat16(o1 - __bfloat162float(h1));
    __nv_bfloat16 l2 = __float2bfloat16(o2 - __bfloat162float(h2));
    __nv_bfloat16 l3 = __float2bfloat16(o3 - __bfloat162float(h3));

    size_t base = (size_t)row * HD + lane * 4;
    *(__nv_bfloat162*)(oh + base)     = __nv_bfloat162(h0, h1);
    *(__nv_bfloat162*)(oh + base + 2) = __nv_bfloat162(h2, h3);
    *(__nv_bfloat162*)(ol + base)     = __nv_bfloat162(l0, l1);
    *(__nv_bfloat162*)(ol + base + 2) = __nv_bfloat162(l2, l3);
}

// ---------------------------------------------------------------------------
// Tensor-core flash attention (bf16 split), causal, GQA.
// CTA = (128 q rows, head). 8 warps x 16 rows. Bk=64 K/V double-buffered.
// ---------------------------------------------------------------------------
#define KVTILE_B 16384                    // 64 rows x 256B
#define ASTAGE_B (4 * KVTILE_B)           // Kh,Kl,Vh,Vl
#define ASM_TOTAL (2 * ASTAGE_B)          // 131072

__device__ __forceinline__ uint32_t swz256(int r, int u) {
    return (uint32_t)(r * 256 + ((u ^ (r & 7)) << 4));
}

__global__ __launch_bounds__(256, 1)
void attn_mma(const __nv_bfloat16* __restrict__ Qh, const __nv_bfloat16* __restrict__ Ql,
              const __nv_bfloat16* __restrict__ Kh, const __nv_bfloat16* __restrict__ Kl,
              const __nv_bfloat16* __restrict__ Vh, const __nv_bfloat16* __restrict__ Vl,
              float* __restrict__ O)
{
    extern __shared__ __align__(1024) char smem[];
    const uint32_t sb = smem_u32(smem);
    const int tid  = threadIdx.x;
    const int lane = tid & 31;
    const int warp = tid >> 5;
    const int qb = (int)gridDim.x - 1 - (int)blockIdx.x;
    const int h  = blockIdx.y;
    const int kvh = h >> 2;
    const int q0 = qb * 128;
    const int NB = 2 * qb + 2;

    // ---- Stage Q through smem, build register fragments (hi then lo)
    uint32_t qfh[8][4], qfl[8][4];
#pragma unroll
    for (int comp = 0; comp < 2; comp++) {
        const __nv_bfloat16* src = comp ? Ql : Qh;
        for (int t = 0; t < 8; t++) {
            int idx = tid + t * 256;
            int r = idx >> 4, u = idx & 15;
            const __nv_bfloat16* gp = src + (size_t)(q0 + r) * QDIM + h * HD + u * 8;
            asm volatile("cp.async.cg.shared.global [%0], [%1], 16;"
                         :: "r"(sb + swz256(r, u)), "l"(gp) : "memory");
        }
        asm volatile("cp.async.commit_group;" ::: "memory");
        asm volatile("cp.async.wait_group 0;" ::: "memory");
        __syncthreads();
        {
            int r = warp * 16 + (lane & 15);
#pragma unroll
            for (int ks = 0; ks < 8; ks++) {
                uint32_t addr = sb + swz256(r, 2 * ks + (lane >> 4));
                if (comp) ldsm4(qfl[ks], addr);
                else      ldsm4(qfh[ks], addr);
            }
        }
        __syncthreads();
    }

    float o[16][4];
#pragma unroll
    for (int i = 0; i < 16; i++)
#pragma unroll
        for (int q = 0; q < 4; q++) o[i][q] = 0.0f;
    float m0 = -1e30f, m1 = -1e30f, l0 = 0.0f, l1 = 0.0f;

    const int row0 = q0 + warp * 16 + (lane >> 2);
    const int row1 = row0 + 8;

    // ---- prologue: load kb=0
    {
        const uint32_t base = sb;
        for (int t = 0; t < 4; t++) {
            int idx = tid + t * 256;
            int r = idx >> 4, u = idx & 15;
            size_t go = (size_t)r * KVDIM + kvh * HD + u * 8;
            uint32_t sw = swz256(r, u);
            asm volatile("cp.async.cg.shared.global [%0], [%1], 16;"
                         :: "r"(base + sw), "l"(Kh + go) : "memory");
            asm volatile("cp.async.cg.shared.global [%0], [%1], 16;"
                         :: "r"(base + KVTILE_B + sw), "l"(Kl + go) : "memory");
            asm volatile("cp.async.cg.shared.global [%0], [%1], 16;"
                         :: "r"(base + 2 * KVTILE_B + sw), "l"(Vh + go) : "memory");
            asm volatile("cp.async.cg.shared.global [%0], [%1], 16;"
                         :: "r"(base + 3 * KVTILE_B + sw), "l"(Vl + go) : "memory");
        }
        asm volatile("cp.async.commit_group;" ::: "memory");
    }

    for (int kb = 0; kb < NB; kb++) {
        // issue next stage load
        if (kb + 1 < NB) {
            const uint32_t base = sb + ((kb + 1) & 1) * ASTAGE_B;
            const int k0n = (kb + 1) * 64;
            for (int t = 0; t < 4; t++) {
                int idx = tid + t * 256;
                int r = idx >> 4, u = idx & 15;
                size_t go = (size_t)(k0n + r) * KVDIM + kvh * HD + u * 8;
                uint32_t sw = swz256(r, u);
                asm volatile("cp.async.cg.shared.global [%0], [%1], 16;"
                             :: "r"(base + sw), "l"(Kh + go) : "memory");
                asm volatile("cp.async.cg.shared.global [%0], [%1], 16;"
                             :: "r"(base + KVTILE_B + sw), "l"(Kl + go) : "memory");
                asm volatile("cp.async.cg.shared.global [%0], [%1], 16;"
                             :: "r"(base + 2 * KVTILE_B + sw), "l"(Vh + go) : "memory");
                asm volatile("cp.async.cg.shared.global [%0], [%1], 16;"
                             :: "r"(base + 3 * KVTILE_B + sw), "l"(Vl + go) : "memory");
            }
            asm volatile("cp.async.commit_group;" ::: "memory");
            asm volatile("cp.async.wait_group 1;" ::: "memory");
        } else {
            asm volatile("cp.async.wait_group 0;" ::: "memory");
        }
        __syncthreads();

        const uint32_t bK = sb + (kb & 1) * ASTAGE_B;
        const int k0 = kb * 64;

        // ---- S = Q K^T (bf16x3)
        float s[8][4];
#pragma unroll
        for (int nt = 0; nt < 8; nt++)
#pragma unroll
            for (int q = 0; q < 4; q++) s[nt][q] = 0.0f;

#pragma unroll
        for (int ks = 0; ks < 8; ks++) {
#pragma unroll
            for (int g = 0; g < 4; g++) {
                uint32_t kh4[4], kl4[4];
                int rr = g * 16 + ((lane >> 3) & 1) * 8 + (lane & 7);
                uint32_t off = swz256(rr, 2 * ks + (lane >> 4));
                ldsm4(kh4, bK + off);
                ldsm4(kl4, bK + KVTILE_B + off);
#pragma unroll
                for (int sel = 0; sel < 2; sel++) {
                    int nt = g * 2 + sel;
                    mma16816(s[nt], qfh[ks], kh4[sel], kh4[sel + 2]);
                    mma16816(s[nt], qfh[ks], kl4[sel], kl4[sel + 2]);
                    mma16816(s[nt], qfl[ks], kh4[sel], kh4[sel + 2]);
                }
            }
        }

        // ---- scale + causal mask
        const bool domask = (k0 + 63) > row0;
#pragma unroll
        for (int nt = 0; nt < 8; nt++) {
            int c0 = k0 + nt * 8 + (lane & 3) * 2;
#pragma unroll
            for (int q = 0; q < 4; q++) s[nt][q] *= RSCALE;
            if (domask) {
                if (c0     > row0) s[nt][0] = -1e30f;
                if (c0 + 1 > row0) s[nt][1] = -1e30f;
                if (c0     > row1) s[nt][2] = -1e30f;
                if (c0 + 1 > row1) s[nt][3] = -1e30f;
            }
        }

        // ---- online softmax
        float mx0 = -1e30f, mx1 = -1e30f;
#pragma unroll
        for (int nt = 0; nt < 8; nt++) {
            mx0 = fmaxf(mx0, fmaxf(s[nt][0], s[nt][1]));
            mx1 = fmaxf(mx1, fmaxf(s[nt][2], s[nt][3]));
        }
        mx0 = fmaxf(mx0, __shfl_xor_sync(0xffffffffu, mx0, 1));
        mx0 = fmaxf(mx0, __shfl_xor_sync(0xffffffffu, mx0, 2));
        mx1 = fmaxf(mx1, __shfl_xor_sync(0xffffffffu, mx1, 1));
        mx1 = fmaxf(mx1, __shfl_xor_sync(0xffffffffu, mx1, 2));

        float mn0 = fmaxf(m0, mx0), mn1 = fmaxf(m1, mx1);
        float a0 = __expf(m0 - mn0), a1 = __expf(m1 - mn1);
        m0 = mn0; m1 = mn1;

        float sum0 = 0.0f, sum1 = 0.0f;
#pragma unroll
        for (int nt = 0; nt < 8; nt++) {
            s[nt][0] = __expf(s[nt][0] - mn0);
            s[nt][1] = __expf(s[nt][1] - mn0);
            s[nt][2] = __expf(s[nt][2] - mn1);
            s[nt][3] = __expf(s[nt][3] - mn1);
            sum0 += s[nt][0] + s[nt][1];
            sum1 += s[nt][2] + s[nt][3];
        }
        sum0 += __shfl_xor_sync(0xffffffffu, sum0, 1);
        sum0 += __shfl_xor_sync(0xffffffffu, sum0, 2);
        sum1 += __shfl_xor_sync(0xffffffffu, sum1, 1);
        sum1 += __shfl_xor_sync(0xffffffffu, sum1, 2);
        l0 = l0 * a0 + sum0;
        l1 = l1 * a1 + sum1;

#pragma unroll
        for (int nt = 0; nt < 16; nt++) {
            o[nt][0] *= a0; o[nt][1] *= a0;
            o[nt][2] *= a1; o[nt][3] *= a1;
        }

        // ---- O += P V (bf16 split P and V)
#pragma unroll
        for (int kt = 0; kt < 4; kt++) {
            uint32_t pah[4], pal[4];
            {
                float e[8] = { s[2*kt][0], s[2*kt][1], s[2*kt][2], s[2*kt][3],
                               s[2*kt+1][0], s[2*kt+1][1], s[2*kt+1][2], s[2*kt+1][3] };
                float hf[8], lf[8];
#pragma unroll
                for (int q = 0; q < 8; q++) {
                    __nv_bfloat16 hb = __float2bfloat16(e[q]);
                    hf[q] = __bfloat162float(hb);
                    lf[q] = e[q] - hf[q];
                }
                pah[0] = pack_bf16(hf[0], hf[1]);
                pah[1] = pack_bf16(hf[2], hf[3]);
                pah[2] = pack_bf16(hf[4], hf[5]);
                pah[3] = pack_bf16(hf[6], hf[7]);
                pal[0] = pack_bf16(lf[0], lf[1]);
                pal[1] = pack_bf16(lf[2], lf[3]);
                pal[2] = pack_bf16(lf[4], lf[5]);
                pal[3] = pack_bf16(lf[6], lf[7]);
            }
            const int j = lane >> 3, ll = lane & 7;
            const int rr = kt * 16 + (j & 1) * 8 + ll;
#pragma unroll
            for (int gn = 0; gn < 8; gn++) {
                uint32_t vh4[4], vl4[4];
                uint32_t off = swz256(rr, gn * 2 + (j >> 1));
                ldsm4t(vh4, bK + 2 * KVTILE_B + off);
                ldsm4t(vl4, bK + 3 * KVTILE_B + off);
#pragma unroll
                for (int sel = 0; sel < 2; sel++) {
                    int nt = gn * 2 + sel;
                    mma16816(o[nt], pah, vh4[sel * 2], vh4[sel * 2 + 1]);
                    mma16816(o[nt], pah, vl4[sel * 2], vl4[sel * 2 + 1]);
                    mma16816(o[nt], pal, vh4[sel * 2], vh4[sel * 2 + 1]);
                }
            }
        }
        __syncthreads();
    }

    // ---- finalize
    const float i0 = 1.0f / l0, i1 = 1.0f / l1;
#pragma unroll
    for (int nt = 0; nt < 16; nt++) {
        int col = h * HD + nt * 8 + (lane & 3) * 2;
        *(float2*)(O + (size_t)row0 * QDIM + col) =
            make_float2(o[nt][0] * i0, o[nt][1] * i0);
        *(float2*)(O + (size_t)row1 * QDIM + col) =
            make_float2(o[nt][2] * i1, o[nt][3] * i1);
    }
}

// ---------------------------------------------------------------------------
extern "C" void kernel_launch(void* const* d_in, const int* in_sizes, int n_in,
                              void* d_out, int out_size)
{
    const float* hidden = (const float*)d_in[0];
    const float* cosb   = (const float*)d_in[1];
    const float* sinb   = (const float*)d_in[2];
    const float* Wq     = (const float*)d_in[3];
    const float* Wk     = (const float*)d_in[4];
    const float* Wv     = (const float*)d_in[5];
    const float* Wo     = (const float*)d_in[6];
    const float* qw     = (const float*)d_in[7];
    const float* kw     = (const float*)d_in[8];
    float* out = (float*)d_out;

    float *Qp, *Kp, *Vp, *AOp;
    cudaGetSymbolAddress((void**)&Qp,  g_Q);
    cudaGetSymbolAddress((void**)&Kp,  g_K);
    cudaGetSymbolAddress((void**)&Vp,  g_V);
    cudaGetSymbolAddress((void**)&AOp, g_AO);

    __nv_bfloat16 *Xh, *Xl, *Wqh, *Wql, *Wkh, *Wkl, *Wvh, *Wvl, *Woh, *Wol, *AOh, *AOl;
    __nv_bfloat16 *Qh2, *Ql2, *Kh2, *Kl2, *Vh2, *Vl2;
    cudaGetSymbolAddress((void**)&Xh,  g_Xhi);  cudaGetSymbolAddress((void**)&Xl,  g_Xlo);
    cudaGetSymbolAddress((void**)&Wqh, g_Wqh);  cudaGetSymbolAddress((void**)&Wql, g_Wql);
    cudaGetSymbolAddress((void**)&Wkh, g_Wkh);  cudaGetSymbolAddress((void**)&Wkl, g_Wkl);
    cudaGetSymbolAddress((void**)&Wvh, g_Wvh);  cudaGetSymbolAddress((void**)&Wvl, g_Wvl);
    cudaGetSymbolAddress((void**)&Woh, g_Woh);  cudaGetSymbolAddress((void**)&Wol, g_Wol);
    cudaGetSymbolAddress((void**)&AOh, g_AOh);  cudaGetSymbolAddress((void**)&AOl, g_AOl);
    cudaGetSymbolAddress((void**)&Qh2, g_Qh2);  cudaGetSymbolAddress((void**)&Ql2, g_Ql2);
    cudaGetSymbolAddress((void**)&Kh2, g_Kh2);  cudaGetSymbolAddress((void**)&Kl2, g_Kl2);
    cudaGetSymbolAddress((void**)&Vh2, g_Vh2);  cudaGetSymbolAddress((void**)&Vl2, g_Vl2);

    cudaFuncSetAttribute(gemm_bf16x3,
                         cudaFuncAttributeMaxDynamicSharedMemorySize, GSM_TOTAL);
    cudaFuncSetAttribute(attn_mma,
                         cudaFuncAttributeMaxDynamicSharedMemorySize, ASM_TOTAL);

    // Split conversions of inputs
    cvt_split<<<(SEQ * HID) / 1024, 256>>>(hidden, Xh, Xl, SEQ * HID);
    cvt_split<<<(QDIM * HID) / 1024, 256>>>(Wq, Wqh, Wql, QDIM * HID);
    cvt_split<<<(KVDIM * HID) / 1024, 256>>>(Wk, Wkh, Wkl, KVDIM * HID);
    cvt_split<<<(KVDIM * HID) / 1024, 256>>>(Wv, Wvh, Wvl, KVDIM * HID);
    cvt_split<<<(HID * QDIM) / 1024, 256>>>(Wo, Woh, Wol, HID * QDIM);

    // Projections (tensor cores, bf16x3)
    gemm_bf16x3<<<dim3(QDIM / 128, SEQ / 128), 256, GSM_TOTAL>>>(
        Xh, Xl, Wqh, Wql, Qp, SEQ, QDIM, HID);
    gemm_bf16x3<<<dim3(KVDIM / 128, SEQ / 128), 256, GSM_TOTAL>>>(
        Xh, Xl, Wkh, Wkl, Kp, SEQ, KVDIM, HID);
    gemm_bf16x3<<<dim3(KVDIM / 128, SEQ / 128), 256, GSM_TOTAL>>>(
        Xh, Xl, Wvh, Wvl, Vp, SEQ, KVDIM, HID);

    // RMSNorm + RoPE -> bf16 hi/lo
    rmsnorm_rope_split<<<(SEQ * NH) / 8, 256>>>(Qp, qw, cosb, sinb, NH, Qh2, Ql2);
    rmsnorm_rope_split<<<(SEQ * NKV) / 8, 256>>>(Kp, kw, cosb, sinb, NKV, Kh2, Kl2);
    cvt_split<<<(SEQ * KVDIM) / 1024, 256>>>(Vp, Vh2, Vl2, SEQ * KVDIM);

    // Tensor-core flash attention
    attn_mma<<<dim3(SEQ / 128, NH), 256, ASM_TOTAL>>>(
        Qh2, Ql2, Kh2, Kl2, Vh2, Vl2, AOp);

    // Output projection
    cvt_split<<<(SEQ * QDIM) / 1024, 256>>>(AOp, AOh, AOl, SEQ * QDIM);
    gemm_bf16x3<<<dim3(HID / 128, SEQ / 128), 256, GSM_TOTAL>>>(
        AOh, AOl, Woh, Wol, out, SEQ, HID, QDIM);
}

// round 8
// speedup vs baseline: 3.0899x; 1.0056x over previous
#include <cuda_runtime.h>
#include <cuda_bf16.h>
#include <stdint.h>
#include <math.h>

// Problem constants (B=1)
#define SEQ   2048
#define HID   4096
#define NH    32
#define NKV   8
#define HD    128
#define QDIM  (NH * HD)   // 4096
#define KVDIM (NKV * HD)  // 1024
#define RSCALE 0.08838834764831845f  // 128^-0.5
#define REPS   1e-6f

// ---------------------------------------------------------------------------
// Scratch (__device__ globals: allocation-free rule)
// ---------------------------------------------------------------------------
__device__ float g_Q[SEQ * QDIM];
__device__ float g_K[SEQ * KVDIM];

__device__ __nv_bfloat16 g_Xhi[SEQ * HID],    g_Xlo[SEQ * HID];
__device__ __nv_bfloat16 g_Wqh[QDIM * HID],   g_Wql[QDIM * HID];
__device__ __nv_bfloat16 g_Wkh[KVDIM * HID],  g_Wkl[KVDIM * HID];
__device__ __nv_bfloat16 g_Wvh[KVDIM * HID],  g_Wvl[KVDIM * HID];
__device__ __nv_bfloat16 g_Woh[HID * QDIM],   g_Wol[HID * QDIM];
__device__ __nv_bfloat16 g_AOh[SEQ * QDIM],   g_AOl[SEQ * QDIM];

__device__ __nv_bfloat16 g_Qh2[SEQ * QDIM],   g_Ql2[SEQ * QDIM];
__device__ __nv_bfloat16 g_Kh2[SEQ * KVDIM],  g_Kl2[SEQ * KVDIM];
__device__ __nv_bfloat16 g_Vh2[SEQ * KVDIM],  g_Vl2[SEQ * KVDIM];

// ---------------------------------------------------------------------------
// PTX helpers (base sm_100-safe)
// ---------------------------------------------------------------------------
__device__ __forceinline__ uint32_t smem_u32(const void* p) {
    uint32_t a;
    asm("{ .reg .u64 t; cvta.to.shared.u64 t, %1; cvt.u32.u64 %0, t; }"
        : "=r"(a) : "l"(p));
    return a;
}

__device__ __forceinline__ void ldsm4(uint32_t* r, uint32_t addr) {
    asm volatile("ldmatrix.sync.aligned.m8n8.x4.shared.b16 {%0,%1,%2,%3}, [%4];"
                 : "=r"(r[0]), "=r"(r[1]), "=r"(r[2]), "=r"(r[3]) : "r"(addr));
}

__device__ __forceinline__ void ldsm4t(uint32_t* r, uint32_t addr) {
    asm volatile("ldmatrix.sync.aligned.m8n8.x4.trans.shared.b16 {%0,%1,%2,%3}, [%4];"
                 : "=r"(r[0]), "=r"(r[1]), "=r"(r[2]), "=r"(r[3]) : "r"(addr));
}

__device__ __forceinline__ void mma16816(float* c, const uint32_t* a,
                                         uint32_t b0, uint32_t b1) {
    asm volatile(
        "mma.sync.aligned.m16n8k16.row.col.f32.bf16.bf16.f32 "
        "{%0,%1,%2,%3}, {%4,%5,%6,%7}, {%8,%9}, {%0,%1,%2,%3};"
        : "+f"(c[0]), "+f"(c[1]), "+f"(c[2]), "+f"(c[3])
        : "r"(a[0]), "r"(a[1]), "r"(a[2]), "r"(a[3]), "r"(b0), "r"(b1));
}

__device__ __forceinline__ uint32_t pack_bf16(float lo, float hi) {
    __nv_bfloat162 t;
    t.x = __float2bfloat16(lo);
    t.y = __float2bfloat16(hi);
    return *(uint32_t*)&t;
}

__device__ __forceinline__ void split2(float a, float b,
                                       __nv_bfloat162* h, __nv_bfloat162* l) {
    __nv_bfloat16 ha = __float2bfloat16(a);
    __nv_bfloat16 hb = __float2bfloat16(b);
    h->x = ha; h->y = hb;
    l->x = __float2bfloat16(a - __bfloat162float(ha));
    l->y = __float2bfloat16(b - __bfloat162float(hb));
}

// ---------------------------------------------------------------------------
// fp32 -> (bf16 hi, bf16 lo) split conversion
// ---------------------------------------------------------------------------
__global__ __launch_bounds__(256) void cvt_split(
    const float* __restrict__ x, __nv_bfloat16* __restrict__ hi,
    __nv_bfloat16* __restrict__ lo, int n)
{
    int i = (blockIdx.x * 256 + threadIdx.x) * 4;
    if (i >= n) return;
    float4 v = *(const float4*)(x + i);
    __nv_bfloat162 h0, l0, h1, l1;
    split2(v.x, v.y, &h0, &l0);
    split2(v.z, v.w, &h1, &l1);
    *(__nv_bfloat162*)(hi + i)     = h0;
    *(__nv_bfloat162*)(hi + i + 2) = h1;
    *(__nv_bfloat162*)(lo + i)     = l0;
    *(__nv_bfloat162*)(lo + i + 2) = l1;
}

// ---------------------------------------------------------------------------
// mma.sync bf16x3 GEMM, 3-stage cp.async pipeline.
// C fp32 (if C != nullptr), else bf16 hi/lo split to Chi/Clo.
// ---------------------------------------------------------------------------
#define TILE_B   16384
#define STAGE_B  (4 * TILE_B)
#define GSM_TOTAL (3 * STAGE_B)          // 196608

__device__ __forceinline__ void load_tile64(
    uint32_t sdst, const __nv_bfloat16* __restrict__ g,
    int row0, int kc, int K, int tid)
{
#pragma unroll
    for (int s = 0; s < 4; s++) {
        int idx = tid + s * 256;
        int r = idx >> 3;
        int u = idx & 7;
        uint32_t sw = (uint32_t)(r * 128 + ((u ^ (r & 7)) << 4));
        const __nv_bfloat16* gp = g + (size_t)(row0 + r) * K + kc * 64 + u * 8;
        asm volatile("cp.async.cg.shared.global [%0], [%1], 16;"
                     :: "r"(sdst + sw), "l"(gp) : "memory");
    }
}

__global__ __launch_bounds__(256)
void gemm_bf16x3(
    const __nv_bfloat16* __restrict__ Ahi, const __nv_bfloat16* __restrict__ Alo,
    const __nv_bfloat16* __restrict__ Bhi, const __nv_bfloat16* __restrict__ Blo,
    float* __restrict__ C,
    __nv_bfloat16* __restrict__ Chi, __nv_bfloat16* __restrict__ Clo,
    int M, int N, int K)
{
    extern __shared__ __align__(1024) char smem[];
    const uint32_t sb = smem_u32(smem);
    const int tid  = threadIdx.x;
    const int lane = tid & 31;
    const int warp = tid >> 5;
    const int wm = warp >> 2;
    const int wn = warp & 3;
    const int bm = blockIdx.y * 128;
    const int bn = blockIdx.x * 128;
    const int NC = K >> 6;

    float acc[4][4][4];
#pragma unroll
    for (int i = 0; i < 4; i++)
#pragma unroll
        for (int j = 0; j < 4; j++)
#pragma unroll
            for (int q = 0; q < 4; q++) acc[i][j][q] = 0.0f;

    // Prologue: stages 0 and 1
#pragma unroll
    for (int c = 0; c < 2; c++) {
        uint32_t b = sb + c * STAGE_B;
        load_tile64(b,              Ahi, bm, c, K, tid);
        load_tile64(b + TILE_B,     Alo, bm, c, K, tid);
        load_tile64(b + 2 * TILE_B, Bhi, bn, c, K, tid);
        load_tile64(b + 3 * TILE_B, Blo, bn, c, K, tid);
        asm volatile("cp.async.commit_group;" ::: "memory");
    }

    const int a_r  = wm * 64 + (lane & 15);
    const int a_ku = lane >> 4;
    const int b_r  = wn * 32 + ((lane >> 3) & 1) * 8 + (lane & 7);
    const int b_ku = lane >> 4;

    int buf = 0;
    for (int c = 0; c < NC; c++) {
        // issue stage c+2 into the buffer freed at the end of iteration c-1
        if (c + 2 < NC) {
            int nb = buf + 2; if (nb >= 3) nb -= 3;
            uint32_t b2 = sb + nb * STAGE_B;
            load_tile64(b2,              Ahi, bm, c + 2, K, tid);
            load_tile64(b2 + TILE_B,     Alo, bm, c + 2, K, tid);
            load_tile64(b2 + 2 * TILE_B, Bhi, bn, c + 2, K, tid);
            load_tile64(b2 + 3 * TILE_B, Blo, bn, c + 2, K, tid);
            asm volatile("cp.async.commit_group;" ::: "memory");
            asm volatile("cp.async.wait_group 2;" ::: "memory");
        } else if (c + 1 < NC) {
            asm volatile("cp.async.wait_group 1;" ::: "memory");
        } else {
            asm volatile("cp.async.wait_group 0;" ::: "memory");
        }
        __syncthreads();

        const uint32_t b = sb + buf * STAGE_B;
        const uint32_t sAh = b;
        const uint32_t sAl = b + TILE_B;
        const uint32_t sBh = b + 2 * TILE_B;
        const uint32_t sBl = b + 3 * TILE_B;

#pragma unroll
        for (int ks = 0; ks < 4; ks++) {
            const int ku0 = ks * 2;
            uint32_t aH[4][4], aL[4][4];
#pragma unroll
            for (int mt = 0; mt < 4; mt++) {
                int r = a_r + mt * 16;
                int ku = ku0 + a_ku;
                uint32_t off = (uint32_t)(r * 128 + ((ku ^ (r & 7)) << 4));
                ldsm4(aH[mt], sAh + off);
                ldsm4(aL[mt], sAl + off);
            }
            uint32_t bH[2][4], bL[2][4];
#pragma unroll
            for (int ntp = 0; ntp < 2; ntp++) {
                int r = b_r + ntp * 16;
                int ku = ku0 + b_ku;
                uint32_t off = (uint32_t)(r * 128 + ((ku ^ (r & 7)) << 4));
                ldsm4(bH[ntp], sBh + off);
                ldsm4(bL[ntp], sBl + off);
            }
#pragma unroll
            for (int mt = 0; mt < 4; mt++) {
#pragma unroll
                for (int nt = 0; nt < 4; nt++) {
                    const int ntp = nt >> 1;
                    const int sel = nt & 1;
                    mma16816(acc[mt][nt], aH[mt], bH[ntp][sel], bH[ntp][sel + 2]);
                    mma16816(acc[mt][nt], aH[mt], bL[ntp][sel], bL[ntp][sel + 2]);
                    mma16816(acc[mt][nt], aL[mt], bH[ntp][sel], bH[ntp][sel + 2]);
                }
            }
        }
        __syncthreads();
        if (++buf == 3) buf = 0;
    }

    // Epilogue
#pragma unroll
    for (int mt = 0; mt < 4; mt++) {
        const int row = bm + wm * 64 + mt * 16 + (lane >> 2);
#pragma unroll
        for (int nt = 0; nt < 4; nt++) {
            const int col = bn + wn * 32 + nt * 8 + (lane & 3) * 2;
            if (C) {
                *(float2*)(C + (size_t)row * N + col) =
                    make_float2(acc[mt][nt][0], acc[mt][nt][1]);
                *(float2*)(C + (size_t)(row + 8) * N + col) =
                    make_float2(acc[mt][nt][2], acc[mt][nt][3]);
            } else {
                __nv_bfloat162 h, l;
                split2(acc[mt][nt][0], acc[mt][nt][1], &h, &l);
                *(__nv_bfloat162*)(Chi + (size_t)row * N + col) = h;
                *(__nv_bfloat162*)(Clo + (size_t)row * N + col) = l;
                split2(acc[mt][nt][2], acc[mt][nt][3], &h, &l);
                *(__nv_bfloat162*)(Chi + (size_t)(row + 8) * N + col) = h;
                *(__nv_bfloat162*)(Clo + (size_t)(row + 8) * N + col) = l;
            }
        }
    }
}

// ---------------------------------------------------------------------------
// Fused RMSNorm + RoPE, writing bf16 hi/lo split directly
// ---------------------------------------------------------------------------
__global__ __launch_bounds__(256) void rmsnorm_rope_split(
    const float* __restrict__ X, const float* __restrict__ w,
    const float* __restrict__ cosb, const float* __restrict__ sinb,
    int nheads, __nv_bfloat16* __restrict__ oh, __nv_bfloat16* __restrict__ ol)
{
    const int row  = blockIdx.x * 8 + (threadIdx.x >> 5);
    const int lane = threadIdx.x & 31;
    const int s    = row / nheads;

    const float* x = X + (size_t)row * HD;
    float4 v = *(const float4*)(x + lane * 4);

    float ss = v.x * v.x + v.y * v.y + v.z * v.z + v.w * v.w;
#pragma unroll
    for (int o = 16; o > 0; o >>= 1) ss += __shfl_xor_sync(0xffffffffu, ss, o);
    const float inv = rsqrtf(ss * (1.0f / 128.0f) + REPS);

    float4 wv = *(const float4*)(w + lane * 4);
    float x0 = v.x * inv * wv.x;
    float x1 = v.y * inv * wv.y;
    float x2 = v.z * inv * wv.z;
    float x3 = v.w * inv * wv.w;

    float p0 = __shfl_xor_sync(0xffffffffu, x0, 16);
    float p1 = __shfl_xor_sync(0xffffffffu, x1, 16);
    float p2 = __shfl_xor_sync(0xffffffffu, x2, 16);
    float p3 = __shfl_xor_sync(0xffffffffu, x3, 16);
    const float sgn = (lane < 16) ? -1.0f : 1.0f;

    const float* cp = cosb + (size_t)s * HD + lane * 4;
    const float* sp = sinb + (size_t)s * HD + lane * 4;
    float4 c = *(const float4*)cp;
    float4 sn = *(const float4*)sp;

    float o0 = x0 * c.x + sgn * p0 * sn.x;
    float o1 = x1 * c.y + sgn * p1 * sn.y;
    float o2 = x2 * c.z + sgn * p2 * sn.z;
    float o3 = x3 * c.w + sgn * p3 * sn.w;

    __nv_bfloat162 h, l;
    size_t base = (size_t)row * HD + lane * 4;
    split2(o0, o1, &h, &l);
    *(__nv_bfloat162*)(oh + base)     = h;
    *(__nv_bfloat162*)(ol + base)     = l;
    split2(o2, o3, &h, &l);
    *(__nv_bfloat162*)(oh + base + 2) = h;
    *(__nv_bfloat162*)(ol + base + 2) = l;
}

// ---------------------------------------------------------------------------
// Tensor-core flash attention (bf16 split), causal, GQA, 3-stage pipeline.
// Writes AO directly as bf16 hi/lo split.
// ---------------------------------------------------------------------------
#define KVTILE_B 16384                    // 64 rows x 256B
#define ASTAGE_B (4 * KVTILE_B)           // Kh,Kl,Vh,Vl
#define ASM_TOTAL (3 * ASTAGE_B)          // 196608

__device__ __forceinline__ uint32_t swz256(int r, int u) {
    return (uint32_t)(r * 256 + ((u ^ (r & 7)) << 4));
}

__device__ __forceinline__ void attn_load_kv(
    uint32_t base, const __nv_bfloat16* __restrict__ Kh,
    const __nv_bfloat16* __restrict__ Kl, const __nv_bfloat16* __restrict__ Vh,
    const __nv_bfloat16* __restrict__ Vl, int k0, int kvh, int tid)
{
#pragma unroll
    for (int t = 0; t < 4; t++) {
        int idx = tid + t * 256;
        int r = idx >> 4, u = idx & 15;
        size_t go = (size_t)(k0 + r) * KVDIM + kvh * HD + u * 8;
        uint32_t sw = swz256(r, u);
        asm volatile("cp.async.cg.shared.global [%0], [%1], 16;"
                     :: "r"(base + sw), "l"(Kh + go) : "memory");
        asm volatile("cp.async.cg.shared.global [%0], [%1], 16;"
                     :: "r"(base + KVTILE_B + sw), "l"(Kl + go) : "memory");
        asm volatile("cp.async.cg.shared.global [%0], [%1], 16;"
                     :: "r"(base + 2 * KVTILE_B + sw), "l"(Vh + go) : "memory");
        asm volatile("cp.async.cg.shared.global [%0], [%1], 16;"
                     :: "r"(base + 3 * KVTILE_B + sw), "l"(Vl + go) : "memory");
    }
}

__global__ __launch_bounds__(256, 1)
void attn_mma(const __nv_bfloat16* __restrict__ Qh, const __nv_bfloat16* __restrict__ Ql,
              const __nv_bfloat16* __restrict__ Kh, const __nv_bfloat16* __restrict__ Kl,
              const __nv_bfloat16* __restrict__ Vh, const __nv_bfloat16* __restrict__ Vl,
              __nv_bfloat16* __restrict__ Ohi, __nv_bfloat16* __restrict__ Olo)
{
    extern __shared__ __align__(1024) char smem[];
    const uint32_t sb = smem_u32(smem);
    const int tid  = threadIdx.x;
    const int lane = tid & 31;
    const int warp = tid >> 5;
    const int qb = (int)gridDim.x - 1 - (int)blockIdx.x;
    const int h  = blockIdx.y;
    const int kvh = h >> 2;
    const int q0 = qb * 128;
    const int NB = 2 * qb + 2;

    // ---- Stage Q through smem, build register fragments (hi then lo)
    uint32_t qfh[8][4], qfl[8][4];
#pragma unroll
    for (int comp = 0; comp < 2; comp++) {
        const __nv_bfloat16* src = comp ? Ql : Qh;
        for (int t = 0; t < 8; t++) {
            int idx = tid + t * 256;
            int r = idx >> 4, u = idx & 15;
            const __nv_bfloat16* gp = src + (size_t)(q0 + r) * QDIM + h * HD + u * 8;
            asm volatile("cp.async.cg.shared.global [%0], [%1], 16;"
                         :: "r"(sb + swz256(r, u)), "l"(gp) : "memory");
        }
        asm volatile("cp.async.commit_group;" ::: "memory");
        asm volatile("cp.async.wait_group 0;" ::: "memory");
        __syncthreads();
        {
            int r = warp * 16 + (lane & 15);
#pragma unroll
            for (int ks = 0; ks < 8; ks++) {
                uint32_t addr = sb + swz256(r, 2 * ks + (lane >> 4));
                if (comp) ldsm4(qfl[ks], addr);
                else      ldsm4(qfh[ks], addr);
            }
        }
        __syncthreads();
    }

    float o[16][4];
#pragma unroll
    for (int i = 0; i < 16; i++)
#pragma unroll
        for (int q = 0; q < 4; q++) o[i][q] = 0.0f;
    float m0 = -1e30f, m1 = -1e30f, l0 = 0.0f, l1 = 0.0f;

    const int row0 = q0 + warp * 16 + (lane >> 2);
    const int row1 = row0 + 8;

    // ---- prologue: stages 0 and 1
    attn_load_kv(sb, Kh, Kl, Vh, Vl, 0, kvh, tid);
    asm volatile("cp.async.commit_group;" ::: "memory");
    if (NB > 1) {
        attn_load_kv(sb + ASTAGE_B, Kh, Kl, Vh, Vl, 64, kvh, tid);
        asm volatile("cp.async.commit_group;" ::: "memory");
    }

    int buf = 0;
    for (int kb = 0; kb < NB; kb++) {
        if (kb + 2 < NB) {
            int nb = buf + 2; if (nb >= 3) nb -= 3;
            attn_load_kv(sb + nb * ASTAGE_B, Kh, Kl, Vh, Vl, (kb + 2) * 64, kvh, tid);
            asm volatile("cp.async.commit_group;" ::: "memory");
            asm volatile("cp.async.wait_group 2;" ::: "memory");
        } else if (kb + 1 < NB) {
            asm volatile("cp.async.wait_group 1;" ::: "memory");
        } else {
            asm volatile("cp.async.wait_group 0;" ::: "memory");
        }
        __syncthreads();

        const uint32_t bK = sb + buf * ASTAGE_B;
        const int k0 = kb * 64;

        // ---- S = Q K^T (bf16x3)
        float s[8][4];
#pragma unroll
        for (int nt = 0; nt < 8; nt++)
#pragma unroll
            for (int q = 0; q < 4; q++) s[nt][q] = 0.0f;

#pragma unroll
        for (int ks = 0; ks < 8; ks++) {
#pragma unroll
            for (int g = 0; g < 4; g++) {
                uint32_t kh4[4], kl4[4];
                int rr = g * 16 + ((lane >> 3) & 1) * 8 + (lane & 7);
                uint32_t off = swz256(rr, 2 * ks + (lane >> 4));
                ldsm4(kh4, bK + off);
                ldsm4(kl4, bK + KVTILE_B + off);
#pragma unroll
                for (int sel = 0; sel < 2; sel++) {
                    int nt = g * 2 + sel;
                    mma16816(s[nt], qfh[ks], kh4[sel], kh4[sel + 2]);
                    mma16816(s[nt], qfh[ks], kl4[sel], kl4[sel + 2]);
                    mma16816(s[nt], qfl[ks], kh4[sel], kh4[sel + 2]);
                }
            }
        }

        // ---- scale + causal mask
        const bool domask = (k0 + 63) > row0;
#pragma unroll
        for (int nt = 0; nt < 8; nt++) {
            int c0 = k0 + nt * 8 + (lane & 3) * 2;
#pragma unroll
            for (int q = 0; q < 4; q++) s[nt][q] *= RSCALE;
            if (domask) {
                if (c0     > row0) s[nt][0] = -1e30f;
                if (c0 + 1 > row0) s[nt][1] = -1e30f;
                if (c0     > row1) s[nt][2] = -1e30f;
                if (c0 + 1 > row1) s[nt][3] = -1e30f;
            }
        }

        // ---- online softmax
        float mx0 = -1e30f, mx1 = -1e30f;
#pragma unroll
        for (int nt = 0; nt < 8; nt++) {
            mx0 = fmaxf(mx0, fmaxf(s[nt][0], s[nt][1]));
            mx1 = fmaxf(mx1, fmaxf(s[nt][2], s[nt][3]));
        }
        mx0 = fmaxf(mx0, __shfl_xor_sync(0xffffffffu, mx0, 1));
        mx0 = fmaxf(mx0, __shfl_xor_sync(0xffffffffu, mx0, 2));
        mx1 = fmaxf(mx1, __shfl_xor_sync(0xffffffffu, mx1, 1));
        mx1 = fmaxf(mx1, __shfl_xor_sync(0xffffffffu, mx1, 2));

        float mn0 = fmaxf(m0, mx0), mn1 = fmaxf(m1, mx1);
        float a0 = __expf(m0 - mn0), a1 = __expf(m1 - mn1);
        m0 = mn0; m1 = mn1;

        float sum0 = 0.0f, sum1 = 0.0f;
#pragma unroll
        for (int nt = 0; nt < 8; nt++) {
            s[nt][0] = __expf(s[nt][0] - mn0);
            s[nt][1] = __expf(s[nt][1] - mn0);
            s[nt][2] = __expf(s[nt][2] - mn1);
            s[nt][3] = __expf(s[nt][3] - mn1);
            sum0 += s[nt][0] + s[nt][1];
            sum1 += s[nt][2] + s[nt][3];
        }
        sum0 += __shfl_xor_sync(0xffffffffu, sum0, 1);
        sum0 += __shfl_xor_sync(0xffffffffu, sum0, 2);
        sum1 += __shfl_xor_sync(0xffffffffu, sum1, 1);
        sum1 += __shfl_xor_sync(0xffffffffu, sum1, 2);
        l0 = l0 * a0 + sum0;
        l1 = l1 * a1 + sum1;

#pragma unroll
        for (int nt = 0; nt < 16; nt++) {
            o[nt][0] *= a0; o[nt][1] *= a0;
            o[nt][2] *= a1; o[nt][3] *= a1;
        }

        // ---- O += P V (bf16 split P and V)
#pragma unroll
        for (int kt = 0; kt < 4; kt++) {
            uint32_t pah[4], pal[4];
            {
                float e[8] = { s[2*kt][0], s[2*kt][1], s[2*kt][2], s[2*kt][3],
                               s[2*kt+1][0], s[2*kt+1][1], s[2*kt+1][2], s[2*kt+1][3] };
                float hf[8], lf[8];
#pragma unroll
                for (int q = 0; q < 8; q++) {
                    __nv_bfloat16 hb = __float2bfloat16(e[q]);
                    hf[q] = __bfloat162float(hb);
                    lf[q] = e[q] - hf[q];
                }
                pah[0] = pack_bf16(hf[0], hf[1]);
                pah[1] = pack_bf16(hf[2], hf[3]);
                pah[2] = pack_bf16(hf[4], hf[5]);
                pah[3] = pack_bf16(hf[6], hf[7]);
                pal[0] = pack_bf16(lf[0], lf[1]);
                pal[1] = pack_bf16(lf[2], lf[3]);
                pal[2] = pack_bf16(lf[4], lf[5]);
                pal[3] = pack_bf16(lf[6], lf[7]);
            }
            const int j = lane >> 3, ll = lane & 7;
            const int rr = kt * 16 + (j & 1) * 8 + ll;
#pragma unroll
            for (int gn = 0; gn < 8; gn++) {
                uint32_t vh4[4], vl4[4];
                uint32_t off = swz256(rr, gn * 2 + (j >> 1));
                ldsm4t(vh4, bK + 2 * KVTILE_B + off);
                ldsm4t(vl4, bK + 3 * KVTILE_B + off);
#pragma unroll
                for (int sel = 0; sel < 2; sel++) {
                    int nt = gn * 2 + sel;
                    mma16816(o[nt], pah, vh4[sel * 2], vh4[sel * 2 + 1]);
                    mma16816(o[nt], pah, vl4[sel * 2], vl4[sel * 2 + 1]);
                    mma16816(o[nt], pal, vh4[sel * 2], vh4[sel * 2 + 1]);
                }
            }
        }
        __syncthreads();
        if (++buf == 3) buf = 0;
    }

    // ---- finalize: write split AO directly
    const float i0 = 1.0f / l0, i1 = 1.0f / l1;
#pragma unroll
    for (int nt = 0; nt < 16; nt++) {
        int col = h * HD + nt * 8 + (lane & 3) * 2;
        __nv_bfloat162 hh, ll2;
        split2(o[nt][0] * i0, o[nt][1] * i0, &hh, &ll2);
        *(__nv_bfloat162*)(Ohi + (size_t)row0 * QDIM + col) = hh;
        *(__nv_bfloat162*)(Olo + (size_t)row0 * QDIM + col) = ll2;
        split2(o[nt][2] * i1, o[nt][3] * i1, &hh, &ll2);
        *(__nv_bfloat162*)(Ohi + (size_t)row1 * QDIM + col) = hh;
        *(__nv_bfloat162*)(Olo + (size_t)row1 * QDIM + col) = ll2;
    }
}

// ---------------------------------------------------------------------------
extern "C" void kernel_launch(void* const* d_in, const int* in_sizes, int n_in,
                              void* d_out, int out_size)
{
    const float* hidden = (const float*)d_in[0];
    const float* cosb   = (const float*)d_in[1];
    const float* sinb   = (const float*)d_in[2];
    const float* Wq     = (const float*)d_in[3];
    const float* Wk     = (const float*)d_in[4];
    const float* Wv     = (const float*)d_in[5];
    const float* Wo     = (const float*)d_in[6];
    const float* qw     = (const float*)d_in[7];
    const float* kw     = (const float*)d_in[8];
    float* out = (float*)d_out;

    float *Qp, *Kp;
    cudaGetSymbolAddress((void**)&Qp,  g_Q);
    cudaGetSymbolAddress((void**)&Kp,  g_K);

    __nv_bfloat16 *Xh, *Xl, *Wqh, *Wql, *Wkh, *Wkl, *Wvh, *Wvl, *Woh, *Wol, *AOh, *AOl;
    __nv_bfloat16 *Qh2, *Ql2, *Kh2, *Kl2, *Vh2, *Vl2;
    cudaGetSymbolAddress((void**)&Xh,  g_Xhi);  cudaGetSymbolAddress((void**)&Xl,  g_Xlo);
    cudaGetSymbolAddress((void**)&Wqh, g_Wqh);  cudaGetSymbolAddress((void**)&Wql, g_Wql);
    cudaGetSymbolAddress((void**)&Wkh, g_Wkh);  cudaGetSymbolAddress((void**)&Wkl, g_Wkl);
    cudaGetSymbolAddress((void**)&Wvh, g_Wvh);  cudaGetSymbolAddress((void**)&Wvl, g_Wvl);
    cudaGetSymbolAddress((void**)&Woh, g_Woh);  cudaGetSymbolAddress((void**)&Wol, g_Wol);
    cudaGetSymbolAddress((void**)&AOh, g_AOh);  cudaGetSymbolAddress((void**)&AOl, g_AOl);
    cudaGetSymbolAddress((void**)&Qh2, g_Qh2);  cudaGetSymbolAddress((void**)&Ql2, g_Ql2);
    cudaGetSymbolAddress((void**)&Kh2, g_Kh2);  cudaGetSymbolAddress((void**)&Kl2, g_Kl2);
    cudaGetSymbolAddress((void**)&Vh2, g_Vh2);  cudaGetSymbolAddress((void**)&Vl2, g_Vl2);

    cudaFuncSetAttribute(gemm_bf16x3,
                         cudaFuncAttributeMaxDynamicSharedMemorySize, GSM_TOTAL);
    cudaFuncSetAttribute(attn_mma,
                         cudaFuncAttributeMaxDynamicSharedMemorySize, ASM_TOTAL);

    // Split conversions of inputs
    cvt_split<<<(SEQ * HID) / 1024, 256>>>(hidden, Xh, Xl, SEQ * HID);
    cvt_split<<<(QDIM * HID) / 1024, 256>>>(Wq, Wqh, Wql, QDIM * HID);
    cvt_split<<<(KVDIM * HID) / 1024, 256>>>(Wk, Wkh, Wkl, KVDIM * HID);
    cvt_split<<<(KVDIM * HID) / 1024, 256>>>(Wv, Wvh, Wvl, KVDIM * HID);
    cvt_split<<<(HID * QDIM) / 1024, 256>>>(Wo, Woh, Wol, HID * QDIM);

    // Projections (tensor cores, bf16x3)
    gemm_bf16x3<<<dim3(QDIM / 128, SEQ / 128), 256, GSM_TOTAL>>>(
        Xh, Xl, Wqh, Wql, Qp, nullptr, nullptr, SEQ, QDIM, HID);
    gemm_bf16x3<<<dim3(KVDIM / 128, SEQ / 128), 256, GSM_TOTAL>>>(
        Xh, Xl, Wkh, Wkl, Kp, nullptr, nullptr, SEQ, KVDIM, HID);
    gemm_bf16x3<<<dim3(KVDIM / 128, SEQ / 128), 256, GSM_TOTAL>>>(
        Xh, Xl, Wvh, Wvl, nullptr, Vh2, Vl2, SEQ, KVDIM, HID);

    // RMSNorm + RoPE -> bf16 hi/lo
    rmsnorm_rope_split<<<(SEQ * NH) / 8, 256>>>(Qp, qw, cosb, sinb, NH, Qh2, Ql2);
    rmsnorm_rope_split<<<(SEQ * NKV) / 8, 256>>>(Kp, kw, cosb, sinb, NKV, Kh2, Kl2);

    // Tensor-core flash attention -> split AO
    attn_mma<<<dim3(SEQ / 128, NH), 256, ASM_TOTAL>>>(
        Qh2, Ql2, Kh2, Kl2, Vh2, Vl2, AOh, AOl);

    // Output projection
    gemm_bf16x3<<<dim3(HID / 128, SEQ / 128), 256, GSM_TOTAL>>>(
        AOh, AOl, Woh, Wol, out, nullptr, nullptr, SEQ, HID, QDIM);
}

// round 9
// speedup vs baseline: 3.1041x; 1.0046x over previous
#include <cuda_runtime.h>
#include <cuda_bf16.h>
#include <stdint.h>
#include <math.h>

// Problem constants (B=1)
#define SEQ   2048
#define HID   4096
#define NH    32
#define NKV   8
#define HD    128
#define QDIM  (NH * HD)   // 4096
#define KVDIM (NKV * HD)  // 1024
#define RSCALE 0.08838834764831845f  // 128^-0.5
#define REPS   1e-6f

// ---------------------------------------------------------------------------
// Scratch (__device__ globals: allocation-free rule)
// ---------------------------------------------------------------------------
__device__ float g_Q[SEQ * QDIM];
__device__ float g_K[SEQ * KVDIM];

__device__ __nv_bfloat16 g_Xhi[SEQ * HID],    g_Xlo[SEQ * HID];
__device__ __nv_bfloat16 g_Wqh[QDIM * HID],   g_Wql[QDIM * HID];
__device__ __nv_bfloat16 g_Wkh[KVDIM * HID],  g_Wkl[KVDIM * HID];
__device__ __nv_bfloat16 g_Wvh[KVDIM * HID],  g_Wvl[KVDIM * HID];
__device__ __nv_bfloat16 g_Woh[HID * QDIM],   g_Wol[HID * QDIM];
__device__ __nv_bfloat16 g_AOh[SEQ * QDIM],   g_AOl[SEQ * QDIM];

__device__ __nv_bfloat16 g_Qh2[SEQ * QDIM],   g_Ql2[SEQ * QDIM];
__device__ __nv_bfloat16 g_Kh2[SEQ * KVDIM],  g_Kl2[SEQ * KVDIM];
__device__ __nv_bfloat16 g_Vh2[SEQ * KVDIM],  g_Vl2[SEQ * KVDIM];

// ---------------------------------------------------------------------------
// PTX helpers (base sm_100-safe)
// ---------------------------------------------------------------------------
__device__ __forceinline__ uint32_t smem_u32(const void* p) {
    uint32_t a;
    asm("{ .reg .u64 t; cvta.to.shared.u64 t, %1; cvt.u32.u64 %0, t; }"
        : "=r"(a) : "l"(p));
    return a;
}

__device__ __forceinline__ void ldsm4(uint32_t* r, uint32_t addr) {
    asm volatile("ldmatrix.sync.aligned.m8n8.x4.shared.b16 {%0,%1,%2,%3}, [%4];"
                 : "=r"(r[0]), "=r"(r[1]), "=r"(r[2]), "=r"(r[3]) : "r"(addr));
}

__device__ __forceinline__ void ldsm4t(uint32_t* r, uint32_t addr) {
    asm volatile("ldmatrix.sync.aligned.m8n8.x4.trans.shared.b16 {%0,%1,%2,%3}, [%4];"
                 : "=r"(r[0]), "=r"(r[1]), "=r"(r[2]), "=r"(r[3]) : "r"(addr));
}

__device__ __forceinline__ void mma16816(float* c, const uint32_t* a,
                                         uint32_t b0, uint32_t b1) {
    asm volatile(
        "mma.sync.aligned.m16n8k16.row.col.f32.bf16.bf16.f32 "
        "{%0,%1,%2,%3}, {%4,%5,%6,%7}, {%8,%9}, {%0,%1,%2,%3};"
        : "+f"(c[0]), "+f"(c[1]), "+f"(c[2]), "+f"(c[3])
        : "r"(a[0]), "r"(a[1]), "r"(a[2]), "r"(a[3]), "r"(b0), "r"(b1));
}

__device__ __forceinline__ uint32_t pack_bf16(float lo, float hi) {
    __nv_bfloat162 t;
    t.x = __float2bfloat16(lo);
    t.y = __float2bfloat16(hi);
    return *(uint32_t*)&t;
}

__device__ __forceinline__ void split2(float a, float b,
                                       __nv_bfloat162* h, __nv_bfloat162* l) {
    __nv_bfloat16 ha = __float2bfloat16(a);
    __nv_bfloat16 hb = __float2bfloat16(b);
    h->x = ha; h->y = hb;
    l->x = __float2bfloat16(a - __bfloat162float(ha));
    l->y = __float2bfloat16(b - __bfloat162float(hb));
}

// ---------------------------------------------------------------------------
// One fused fp32 -> (bf16 hi, bf16 lo) split for X + all 4 weights.
// Block regions (256 thr, 1024 elems each):
//   X:  [0, 8192)   Wq: [8192, 24576)  Wk: [24576, 28672)
//   Wv: [28672, 32768)  Wo: [32768, 49152)
// ---------------------------------------------------------------------------
#define CVT_BLOCKS 49152

__global__ __launch_bounds__(256) void cvt_all(
    const float* __restrict__ x,  __nv_bfloat16* __restrict__ xh,  __nv_bfloat16* __restrict__ xl,
    const float* __restrict__ wq, __nv_bfloat16* __restrict__ wqh, __nv_bfloat16* __restrict__ wql,
    const float* __restrict__ wk, __nv_bfloat16* __restrict__ wkh, __nv_bfloat16* __restrict__ wkl,
    const float* __restrict__ wv, __nv_bfloat16* __restrict__ wvh, __nv_bfloat16* __restrict__ wvl,
    const float* __restrict__ wo, __nv_bfloat16* __restrict__ woh, __nv_bfloat16* __restrict__ wol)
{
    const int b = blockIdx.x;
    const float* src;
    __nv_bfloat16 *hi, *lo;
    int base;
    if (b < 8192)       { src = x;  hi = xh;  lo = xl;  base = 0; }
    else if (b < 24576) { src = wq; hi = wqh; lo = wql; base = 8192; }
    else if (b < 28672) { src = wk; hi = wkh; lo = wkl; base = 24576; }
    else if (b < 32768) { src = wv; hi = wvh; lo = wvl; base = 28672; }
    else                { src = wo; hi = woh; lo = wol; base = 32768; }

    const int i = ((b - base) * 256 + threadIdx.x) * 4;
    float4 v = *(const float4*)(src + i);
    __nv_bfloat162 h0, l0, h1, l1;
    split2(v.x, v.y, &h0, &l0);
    split2(v.z, v.w, &h1, &l1);
    *(__nv_bfloat162*)(hi + i)     = h0;
    *(__nv_bfloat162*)(hi + i + 2) = h1;
    *(__nv_bfloat162*)(lo + i)     = l0;
    *(__nv_bfloat162*)(lo + i + 2) = l1;
}

// ---------------------------------------------------------------------------
// mma.sync bf16x3 GEMM, 3-stage cp.async pipeline, single sync per chunk.
// C fp32 (if C != nullptr), else bf16 hi/lo split to Chi/Clo.
// ---------------------------------------------------------------------------
#define TILE_B   16384
#define STAGE_B  (4 * TILE_B)
#define GSM_TOTAL (3 * STAGE_B)          // 196608

__device__ __forceinline__ void load_tile64(
    uint32_t sdst, const __nv_bfloat16* __restrict__ g,
    int row0, int kc, int K, int tid)
{
#pragma unroll
    for (int s = 0; s < 4; s++) {
        int idx = tid + s * 256;
        int r = idx >> 3;
        int u = idx & 7;
        uint32_t sw = (uint32_t)(r * 128 + ((u ^ (r & 7)) << 4));
        const __nv_bfloat16* gp = g + (size_t)(row0 + r) * K + kc * 64 + u * 8;
        asm volatile("cp.async.cg.shared.global [%0], [%1], 16;"
                     :: "r"(sdst + sw), "l"(gp) : "memory");
    }
}

__global__ __launch_bounds__(256)
void gemm_bf16x3(
    const __nv_bfloat16* __restrict__ Ahi, const __nv_bfloat16* __restrict__ Alo,
    const __nv_bfloat16* __restrict__ Bhi, const __nv_bfloat16* __restrict__ Blo,
    float* __restrict__ C,
    __nv_bfloat16* __restrict__ Chi, __nv_bfloat16* __restrict__ Clo,
    int M, int N, int K)
{
    extern __shared__ __align__(1024) char smem[];
    const uint32_t sb = smem_u32(smem);
    const int tid  = threadIdx.x;
    const int lane = tid & 31;
    const int warp = tid >> 5;
    const int wm = warp >> 2;
    const int wn = warp & 3;
    const int bm = blockIdx.y * 128;
    const int bn = blockIdx.x * 128;
    const int NC = K >> 6;

    float acc[4][4][4];
#pragma unroll
    for (int i = 0; i < 4; i++)
#pragma unroll
        for (int j = 0; j < 4; j++)
#pragma unroll
            for (int q = 0; q < 4; q++) acc[i][j][q] = 0.0f;

    // Prologue: stages 0 and 1
#pragma unroll
    for (int c = 0; c < 2; c++) {
        uint32_t b = sb + c * STAGE_B;
        load_tile64(b,              Ahi, bm, c, K, tid);
        load_tile64(b + TILE_B,     Alo, bm, c, K, tid);
        load_tile64(b + 2 * TILE_B, Bhi, bn, c, K, tid);
        load_tile64(b + 3 * TILE_B, Blo, bn, c, K, tid);
        asm volatile("cp.async.commit_group;" ::: "memory");
    }

    const int a_r  = wm * 64 + (lane & 15);
    const int a_ku = lane >> 4;
    const int b_r  = wn * 32 + ((lane >> 3) & 1) * 8 + (lane & 7);
    const int b_ku = lane >> 4;

    int buf = 0;
    for (int c = 0; c < NC; c++) {
        if (c + 1 < NC)
            asm volatile("cp.async.wait_group 1;" ::: "memory");
        else
            asm volatile("cp.async.wait_group 0;" ::: "memory");
        __syncthreads();   // chunk c visible AND all warps done with chunk c-1

        // issue chunk c+2 into the buffer that held chunk c-1
        if (c + 2 < NC) {
            int nb = buf + 2; if (nb >= 3) nb -= 3;
            uint32_t b2 = sb + nb * STAGE_B;
            load_tile64(b2,              Ahi, bm, c + 2, K, tid);
            load_tile64(b2 + TILE_B,     Alo, bm, c + 2, K, tid);
            load_tile64(b2 + 2 * TILE_B, Bhi, bn, c + 2, K, tid);
            load_tile64(b2 + 3 * TILE_B, Blo, bn, c + 2, K, tid);
            asm volatile("cp.async.commit_group;" ::: "memory");
        }

        const uint32_t b = sb + buf * STAGE_B;
        const uint32_t sAh = b;
        const uint32_t sAl = b + TILE_B;
        const uint32_t sBh = b + 2 * TILE_B;
        const uint32_t sBl = b + 3 * TILE_B;

#pragma unroll
        for (int ks = 0; ks < 4; ks++) {
            const int ku0 = ks * 2;
            uint32_t aH[4][4], aL[4][4];
#pragma unroll
            for (int mt = 0; mt < 4; mt++) {
                int r = a_r + mt * 16;
                int ku = ku0 + a_ku;
                uint32_t off = (uint32_t)(r * 128 + ((ku ^ (r & 7)) << 4));
                ldsm4(aH[mt], sAh + off);
                ldsm4(aL[mt], sAl + off);
            }
            uint32_t bH[2][4], bL[2][4];
#pragma unroll
            for (int ntp = 0; ntp < 2; ntp++) {
                int r = b_r + ntp * 16;
                int ku = ku0 + b_ku;
                uint32_t off = (uint32_t)(r * 128 + ((ku ^ (r & 7)) << 4));
                ldsm4(bH[ntp], sBh + off);
                ldsm4(bL[ntp], sBl + off);
            }
#pragma unroll
            for (int mt = 0; mt < 4; mt++) {
#pragma unroll
                for (int nt = 0; nt < 4; nt++) {
                    const int ntp = nt >> 1;
                    const int sel = nt & 1;
                    mma16816(acc[mt][nt], aH[mt], bH[ntp][sel], bH[ntp][sel + 2]);
                    mma16816(acc[mt][nt], aH[mt], bL[ntp][sel], bL[ntp][sel + 2]);
                    mma16816(acc[mt][nt], aL[mt], bH[ntp][sel], bH[ntp][sel + 2]);
                }
            }
        }
        if (++buf == 3) buf = 0;
    }

    // Epilogue
#pragma unroll
    for (int mt = 0; mt < 4; mt++) {
        const int row = bm + wm * 64 + mt * 16 + (lane >> 2);
#pragma unroll
        for (int nt = 0; nt < 4; nt++) {
            const int col = bn + wn * 32 + nt * 8 + (lane & 3) * 2;
            if (C) {
                *(float2*)(C + (size_t)row * N + col) =
                    make_float2(acc[mt][nt][0], acc[mt][nt][1]);
                *(float2*)(C + (size_t)(row + 8) * N + col) =
                    make_float2(acc[mt][nt][2], acc[mt][nt][3]);
            } else {
                __nv_bfloat162 h, l;
                split2(acc[mt][nt][0], acc[mt][nt][1], &h, &l);
                *(__nv_bfloat162*)(Chi + (size_t)row * N + col) = h;
                *(__nv_bfloat162*)(Clo + (size_t)row * N + col) = l;
                split2(acc[mt][nt][2], acc[mt][nt][3], &h, &l);
                *(__nv_bfloat162*)(Chi + (size_t)(row + 8) * N + col) = h;
                *(__nv_bfloat162*)(Clo + (size_t)(row + 8) * N + col) = l;
            }
        }
    }
}

// ---------------------------------------------------------------------------
// Fused RMSNorm + RoPE for BOTH Q and K in one launch, bf16 hi/lo out.
// Blocks [0, 8192): Q rows; [8192, 10240): K rows. 8 rows per block.
// ---------------------------------------------------------------------------
#define RMS_BLOCKS (8192 + 2048)

__global__ __launch_bounds__(256) void rms_both(
    const float* __restrict__ Qf, const float* __restrict__ Kf,
    const float* __restrict__ qw, const float* __restrict__ kw,
    const float* __restrict__ cosb, const float* __restrict__ sinb,
    __nv_bfloat16* __restrict__ qh, __nv_bfloat16* __restrict__ ql,
    __nv_bfloat16* __restrict__ kh, __nv_bfloat16* __restrict__ kl)
{
    const int b = blockIdx.x;
    const float* X;
    const float* w;
    __nv_bfloat16 *oh, *ol;
    int nheads, row;
    if (b < 8192) { X = Qf; w = qw; oh = qh; ol = ql; nheads = NH;  row = b * 8; }
    else          { X = Kf; w = kw; oh = kh; ol = kl; nheads = NKV; row = (b - 8192) * 8; }
    row += threadIdx.x >> 5;
    const int lane = threadIdx.x & 31;
    const int s = row / nheads;

    const float* x = X + (size_t)row * HD;
    float4 v = *(const float4*)(x + lane * 4);

    float ss = v.x * v.x + v.y * v.y + v.z * v.z + v.w * v.w;
#pragma unroll
    for (int o = 16; o > 0; o >>= 1) ss += __shfl_xor_sync(0xffffffffu, ss, o);
    const float inv = rsqrtf(ss * (1.0f / 128.0f) + REPS);

    float4 wv = *(const float4*)(w + lane * 4);
    float x0 = v.x * inv * wv.x;
    float x1 = v.y * inv * wv.y;
    float x2 = v.z * inv * wv.z;
    float x3 = v.w * inv * wv.w;

    float p0 = __shfl_xor_sync(0xffffffffu, x0, 16);
    float p1 = __shfl_xor_sync(0xffffffffu, x1, 16);
    float p2 = __shfl_xor_sync(0xffffffffu, x2, 16);
    float p3 = __shfl_xor_sync(0xffffffffu, x3, 16);
    const float sgn = (lane < 16) ? -1.0f : 1.0f;

    const float* cp = cosb + (size_t)s * HD + lane * 4;
    const float* sp = sinb + (size_t)s * HD + lane * 4;
    float4 c = *(const float4*)cp;
    float4 sn = *(const float4*)sp;

    float o0 = x0 * c.x + sgn * p0 * sn.x;
    float o1 = x1 * c.y + sgn * p1 * sn.y;
    float o2 = x2 * c.z + sgn * p2 * sn.z;
    float o3 = x3 * c.w + sgn * p3 * sn.w;

    __nv_bfloat162 h, l;
    size_t base = (size_t)row * HD + lane * 4;
    split2(o0, o1, &h, &l);
    *(__nv_bfloat162*)(oh + base)     = h;
    *(__nv_bfloat162*)(ol + base)     = l;
    split2(o2, o3, &h, &l);
    *(__nv_bfloat162*)(oh + base + 2) = h;
    *(__nv_bfloat162*)(ol + base + 2) = l;
}

// ---------------------------------------------------------------------------
// Tensor-core flash attention (bf16 split), causal, GQA, 3-stage pipeline,
// single sync per KV block. Writes AO directly as bf16 hi/lo split.
// ---------------------------------------------------------------------------
#define KVTILE_B 16384                    // 64 rows x 256B
#define ASTAGE_B (4 * KVTILE_B)           // Kh,Kl,Vh,Vl
#define ASM_TOTAL (3 * ASTAGE_B)          // 196608

__device__ __forceinline__ uint32_t swz256(int r, int u) {
    return (uint32_t)(r * 256 + ((u ^ (r & 7)) << 4));
}

__device__ __forceinline__ void attn_load_kv(
    uint32_t base, const __nv_bfloat16* __restrict__ Kh,
    const __nv_bfloat16* __restrict__ Kl, const __nv_bfloat16* __restrict__ Vh,
    const __nv_bfloat16* __restrict__ Vl, int k0, int kvh, int tid)
{
#pragma unroll
    for (int t = 0; t < 4; t++) {
        int idx = tid + t * 256;
        int r = idx >> 4, u = idx & 15;
        size_t go = (size_t)(k0 + r) * KVDIM + kvh * HD + u * 8;
        uint32_t sw = swz256(r, u);
        asm volatile("cp.async.cg.shared.global [%0], [%1], 16;"
                     :: "r"(base + sw), "l"(Kh + go) : "memory");
        asm volatile("cp.async.cg.shared.global [%0], [%1], 16;"
                     :: "r"(base + KVTILE_B + sw), "l"(Kl + go) : "memory");
        asm volatile("cp.async.cg.shared.global [%0], [%1], 16;"
                     :: "r"(base + 2 * KVTILE_B + sw), "l"(Vh + go) : "memory");
        asm volatile("cp.async.cg.shared.global [%0], [%1], 16;"
                     :: "r"(base + 3 * KVTILE_B + sw), "l"(Vl + go) : "memory");
    }
}

__global__ __launch_bounds__(256, 1)
void attn_mma(const __nv_bfloat16* __restrict__ Qh, const __nv_bfloat16* __restrict__ Ql,
              const __nv_bfloat16* __restrict__ Kh, const __nv_bfloat16* __restrict__ Kl,
              const __nv_bfloat16* __restrict__ Vh, const __nv_bfloat16* __restrict__ Vl,
              __nv_bfloat16* __restrict__ Ohi, __nv_bfloat16* __restrict__ Olo)
{
    extern __shared__ __align__(1024) char smem[];
    const uint32_t sb = smem_u32(smem);
    const int tid  = threadIdx.x;
    const int lane = tid & 31;
    const int warp = tid >> 5;
    const int qb = (int)gridDim.x - 1 - (int)blockIdx.x;
    const int h  = blockIdx.y;
    const int kvh = h >> 2;
    const int q0 = qb * 128;
    const int NB = 2 * qb + 2;

    // ---- Stage Q through smem, build register fragments (hi then lo)
    uint32_t qfh[8][4], qfl[8][4];
#pragma unroll
    for (int comp = 0; comp < 2; comp++) {
        const __nv_bfloat16* src = comp ? Ql : Qh;
        for (int t = 0; t < 8; t++) {
            int idx = tid + t * 256;
            int r = idx >> 4, u = idx & 15;
            const __nv_bfloat16* gp = src + (size_t)(q0 + r) * QDIM + h * HD + u * 8;
            asm volatile("cp.async.cg.shared.global [%0], [%1], 16;"
                         :: "r"(sb + swz256(r, u)), "l"(gp) : "memory");
        }
        asm volatile("cp.async.commit_group;" ::: "memory");
        asm volatile("cp.async.wait_group 0;" ::: "memory");
        __syncthreads();
        {
            int r = warp * 16 + (lane & 15);
#pragma unroll
            for (int ks = 0; ks < 8; ks++) {
                uint32_t addr = sb + swz256(r, 2 * ks + (lane >> 4));
                if (comp) ldsm4(qfl[ks], addr);
                else      ldsm4(qfh[ks], addr);
            }
        }
        __syncthreads();
    }

    float o[16][4];
#pragma unroll
    for (int i = 0; i < 16; i++)
#pragma unroll
        for (int q = 0; q < 4; q++) o[i][q] = 0.0f;
    float m0 = -1e30f, m1 = -1e30f, l0 = 0.0f, l1 = 0.0f;

    const int row0 = q0 + warp * 16 + (lane >> 2);
    const int row1 = row0 + 8;

    // ---- prologue: stages 0 and 1
    attn_load_kv(sb, Kh, Kl, Vh, Vl, 0, kvh, tid);
    asm volatile("cp.async.commit_group;" ::: "memory");
    if (NB > 1) {
        attn_load_kv(sb + ASTAGE_B, Kh, Kl, Vh, Vl, 64, kvh, tid);
        asm volatile("cp.async.commit_group;" ::: "memory");
    }

    int buf = 0;
    for (int kb = 0; kb < NB; kb++) {
        if (kb + 1 < NB)
            asm volatile("cp.async.wait_group 1;" ::: "memory");
        else
            asm volatile("cp.async.wait_group 0;" ::: "memory");
        __syncthreads();   // block kb visible AND all warps done with block kb-1

        if (kb + 2 < NB) {
            int nb = buf + 2; if (nb >= 3) nb -= 3;
            attn_load_kv(sb + nb * ASTAGE_B, Kh, Kl, Vh, Vl, (kb + 2) * 64, kvh, tid);
            asm volatile("cp.async.commit_group;" ::: "memory");
        }

        const uint32_t bK = sb + buf * ASTAGE_B;
        const int k0 = kb * 64;

        // ---- S = Q K^T (bf16x3)
        float s[8][4];
#pragma unroll
        for (int nt = 0; nt < 8; nt++)
#pragma unroll
            for (int q = 0; q < 4; q++) s[nt][q] = 0.0f;

#pragma unroll
        for (int ks = 0; ks < 8; ks++) {
#pragma unroll
            for (int g = 0; g < 4; g++) {
                uint32_t kh4[4], kl4[4];
                int rr = g * 16 + ((lane >> 3) & 1) * 8 + (lane & 7);
                uint32_t off = swz256(rr, 2 * ks + (lane >> 4));
                ldsm4(kh4, bK + off);
                ldsm4(kl4, bK + KVTILE_B + off);
#pragma unroll
                for (int sel = 0; sel < 2; sel++) {
                    int nt = g * 2 + sel;
                    mma16816(s[nt], qfh[ks], kh4[sel], kh4[sel + 2]);
                    mma16816(s[nt], qfh[ks], kl4[sel], kl4[sel + 2]);
                    mma16816(s[nt], qfl[ks], kh4[sel], kh4[sel + 2]);
                }
            }
        }

        // ---- scale + causal mask
        const bool domask = (k0 + 63) > row0;
#pragma unroll
        for (int nt = 0; nt < 8; nt++) {
            int c0 = k0 + nt * 8 + (lane & 3) * 2;
#pragma unroll
            for (int q = 0; q < 4; q++) s[nt][q] *= RSCALE;
            if (domask) {
                if (c0     > row0) s[nt][0] = -1e30f;
                if (c0 + 1 > row0) s[nt][1] = -1e30f;
                if (c0     > row1) s[nt][2] = -1e30f;
                if (c0 + 1 > row1) s[nt][3] = -1e30f;
            }
        }

        // ---- online softmax
        float mx0 = -1e30f, mx1 = -1e30f;
#pragma unroll
        for (int nt = 0; nt < 8; nt++) {
            mx0 = fmaxf(mx0, fmaxf(s[nt][0], s[nt][1]));
            mx1 = fmaxf(mx1, fmaxf(s[nt][2], s[nt][3]));
        }
        mx0 = fmaxf(mx0, __shfl_xor_sync(0xffffffffu, mx0, 1));
        mx0 = fmaxf(mx0, __shfl_xor_sync(0xffffffffu, mx0, 2));
        mx1 = fmaxf(mx1, __shfl_xor_sync(0xffffffffu, mx1, 1));
        mx1 = fmaxf(mx1, __shfl_xor_sync(0xffffffffu, mx1, 2));

        float mn0 = fmaxf(m0, mx0), mn1 = fmaxf(m1, mx1);
        float a0 = __expf(m0 - mn0), a1 = __expf(m1 - mn1);
        m0 = mn0; m1 = mn1;

        float sum0 = 0.0f, sum1 = 0.0f;
#pragma unroll
        for (int nt = 0; nt < 8; nt++) {
            s[nt][0] = __expf(s[nt][0] - mn0);
            s[nt][1] = __expf(s[nt][1] - mn0);
            s[nt][2] = __expf(s[nt][2] - mn1);
            s[nt][3] = __expf(s[nt][3] - mn1);
            sum0 += s[nt][0] + s[nt][1];
            sum1 += s[nt][2] + s[nt][3];
        }
        sum0 += __shfl_xor_sync(0xffffffffu, sum0, 1);
        sum0 += __shfl_xor_sync(0xffffffffu, sum0, 2);
        sum1 += __shfl_xor_sync(0xffffffffu, sum1, 1);
        sum1 += __shfl_xor_sync(0xffffffffu, sum1, 2);
        l0 = l0 * a0 + sum0;
        l1 = l1 * a1 + sum1;

#pragma unroll
        for (int nt = 0; nt < 16; nt++) {
            o[nt][0] *= a0; o[nt][1] *= a0;
            o[nt][2] *= a1; o[nt][3] *= a1;
        }

        // ---- O += P V (bf16 split P and V)
#pragma unroll
        for (int kt = 0; kt < 4; kt++) {
            uint32_t pah[4], pal[4];
            {
                float e[8] = { s[2*kt][0], s[2*kt][1], s[2*kt][2], s[2*kt][3],
                               s[2*kt+1][0], s[2*kt+1][1], s[2*kt+1][2], s[2*kt+1][3] };
                float hf[8], lf[8];
#pragma unroll
                for (int q = 0; q < 8; q++) {
                    __nv_bfloat16 hb = __float2bfloat16(e[q]);
                    hf[q] = __bfloat162float(hb);
                    lf[q] = e[q] - hf[q];
                }
                pah[0] = pack_bf16(hf[0], hf[1]);
                pah[1] = pack_bf16(hf[2], hf[3]);
                pah[2] = pack_bf16(hf[4], hf[5]);
                pah[3] = pack_bf16(hf[6], hf[7]);
                pal[0] = pack_bf16(lf[0], lf[1]);
                pal[1] = pack_bf16(lf[2], lf[3]);
                pal[2] = pack_bf16(lf[4], lf[5]);
                pal[3] = pack_bf16(lf[6], lf[7]);
            }
            const int j = lane >> 3, ll = lane & 7;
            const int rr = kt * 16 + (j & 1) * 8 + ll;
#pragma unroll
            for (int gn = 0; gn < 8; gn++) {
                uint32_t vh4[4], vl4[4];
                uint32_t off = swz256(rr, gn * 2 + (j >> 1));
                ldsm4t(vh4, bK + 2 * KVTILE_B + off);
                ldsm4t(vl4, bK + 3 * KVTILE_B + off);
#pragma unroll
                for (int sel = 0; sel < 2; sel++) {
                    int nt = gn * 2 + sel;
                    mma16816(o[nt], pah, vh4[sel * 2], vh4[sel * 2 + 1]);
                    mma16816(o[nt], pah, vl4[sel * 2], vl4[sel * 2 + 1]);
                    mma16816(o[nt], pal, vh4[sel * 2], vh4[sel * 2 + 1]);
                }
            }
        }
        if (++buf == 3) buf = 0;
    }

    // ---- finalize: write split AO directly
    const float i0 = 1.0f / l0, i1 = 1.0f / l1;
#pragma unroll
    for (int nt = 0; nt < 16; nt++) {
        int col = h * HD + nt * 8 + (lane & 3) * 2;
        __nv_bfloat162 hh, ll2;
        split2(o[nt][0] * i0, o[nt][1] * i0, &hh, &ll2);
        *(__nv_bfloat162*)(Ohi + (size_t)row0 * QDIM + col) = hh;
        *(__nv_bfloat162*)(Olo + (size_t)row0 * QDIM + col) = ll2;
        split2(o[nt][2] * i1, o[nt][3] * i1, &hh, &ll2);
        *(__nv_bfloat162*)(Ohi + (size_t)row1 * QDIM + col) = hh;
        *(__nv_bfloat162*)(Olo + (size_t)row1 * QDIM + col) = ll2;
    }
}

// ---------------------------------------------------------------------------
extern "C" void kernel_launch(void* const* d_in, const int* in_sizes, int n_in,
                              void* d_out, int out_size)
{
    const float* hidden = (const float*)d_in[0];
    const float* cosb   = (const float*)d_in[1];
    const float* sinb   = (const float*)d_in[2];
    const float* Wq     = (const float*)d_in[3];
    const float* Wk     = (const float*)d_in[4];
    const float* Wv     = (const float*)d_in[5];
    const float* Wo     = (const float*)d_in[6];
    const float* qw     = (const float*)d_in[7];
    const float* kw     = (const float*)d_in[8];
    float* out = (float*)d_out;

    float *Qp, *Kp;
    cudaGetSymbolAddress((void**)&Qp,  g_Q);
    cudaGetSymbolAddress((void**)&Kp,  g_K);

    __nv_bfloat16 *Xh, *Xl, *Wqh, *Wql, *Wkh, *Wkl, *Wvh, *Wvl, *Woh, *Wol, *AOh, *AOl;
    __nv_bfloat16 *Qh2, *Ql2, *Kh2, *Kl2, *Vh2, *Vl2;
    cudaGetSymbolAddress((void**)&Xh,  g_Xhi);  cudaGetSymbolAddress((void**)&Xl,  g_Xlo);
    cudaGetSymbolAddress((void**)&Wqh, g_Wqh);  cudaGetSymbolAddress((void**)&Wql, g_Wql);
    cudaGetSymbolAddress((void**)&Wkh, g_Wkh);  cudaGetSymbolAddress((void**)&Wkl, g_Wkl);
    cudaGetSymbolAddress((void**)&Wvh, g_Wvh);  cudaGetSymbolAddress((void**)&Wvl, g_Wvl);
    cudaGetSymbolAddress((void**)&Woh, g_Woh);  cudaGetSymbolAddress((void**)&Wol, g_Wol);
    cudaGetSymbolAddress((void**)&AOh, g_AOh);  cudaGetSymbolAddress((void**)&AOl, g_AOl);
    cudaGetSymbolAddress((void**)&Qh2, g_Qh2);  cudaGetSymbolAddress((void**)&Ql2, g_Ql2);
    cudaGetSymbolAddress((void**)&Kh2, g_Kh2);  cudaGetSymbolAddress((void**)&Kl2, g_Kl2);
    cudaGetSymbolAddress((void**)&Vh2, g_Vh2);  cudaGetSymbolAddress((void**)&Vl2, g_Vl2);

    cudaFuncSetAttribute(gemm_bf16x3,
                         cudaFuncAttributeMaxDynamicSharedMemorySize, GSM_TOTAL);
    cudaFuncSetAttribute(attn_mma,
                         cudaFuncAttributeMaxDynamicSharedMemorySize, ASM_TOTAL);

    // L0: all split conversions in one launch
    cvt_all<<<CVT_BLOCKS, 256>>>(hidden, Xh, Xl, Wq, Wqh, Wql, Wk, Wkh, Wkl,
                                 Wv, Wvh, Wvl, Wo, Woh, Wol);

    // L1-L3: projections (tensor cores, bf16x3)
    gemm_bf16x3<<<dim3(QDIM / 128, SEQ / 128), 256, GSM_TOTAL>>>(
        Xh, Xl, Wqh, Wql, Qp, nullptr, nullptr, SEQ, QDIM, HID);
    gemm_bf16x3<<<dim3(KVDIM / 128, SEQ / 128), 256, GSM_TOTAL>>>(
        Xh, Xl, Wkh, Wkl, Kp, nullptr, nullptr, SEQ, KVDIM, HID);
    gemm_bf16x3<<<dim3(KVDIM / 128, SEQ / 128), 256, GSM_TOTAL>>>(
        Xh, Xl, Wvh, Wvl, nullptr, Vh2, Vl2, SEQ, KVDIM, HID);

    // L4: RMSNorm + RoPE for Q and K in one launch
    rms_both<<<RMS_BLOCKS, 256>>>(Qp, Kp, qw, kw, cosb, sinb,
                                  Qh2, Ql2, Kh2, Kl2);

    // L5: tensor-core flash attention -> split AO
    attn_mma<<<dim3(SEQ / 128, NH), 256, ASM_TOTAL>>>(
        Qh2, Ql2, Kh2, Kl2, Vh2, Vl2, AOh, AOl);

    // L6: output projection
    gemm_bf16x3<<<dim3(HID / 128, SEQ / 128), 256, GSM_TOTAL>>>(
        AOh, AOl, Woh, Wol, out, nullptr, nullptr, SEQ, HID, QDIM);
}

// round 10
// speedup vs baseline: 3.1681x; 1.0206x over previous
#include <cuda_runtime.h>
#include <cuda_bf16.h>
#include <stdint.h>
#include <math.h>

// Problem constants (B=1)
#define SEQ   2048
#define HID   4096
#define NH    32
#define NKV   8
#define HD    128
#define QDIM  (NH * HD)   // 4096
#define KVDIM (NKV * HD)  // 1024
#define RSCALE 0.08838834764831845f  // 128^-0.5
#define REPS   1e-6f

// ---------------------------------------------------------------------------
// Scratch (__device__ globals: allocation-free rule)
// ---------------------------------------------------------------------------
__device__ float g_Q[SEQ * QDIM];
__device__ float g_K[SEQ * KVDIM];

__device__ __nv_bfloat16 g_Xhi[SEQ * HID],    g_Xlo[SEQ * HID];
__device__ __nv_bfloat16 g_Wqh[QDIM * HID],   g_Wql[QDIM * HID];
__device__ __nv_bfloat16 g_Wkh[KVDIM * HID],  g_Wkl[KVDIM * HID];
__device__ __nv_bfloat16 g_Wvh[KVDIM * HID],  g_Wvl[KVDIM * HID];
__device__ __nv_bfloat16 g_Woh[HID * QDIM],   g_Wol[HID * QDIM];
__device__ __nv_bfloat16 g_AOh[SEQ * QDIM],   g_AOl[SEQ * QDIM];

__device__ __nv_bfloat16 g_Qh2[SEQ * QDIM],   g_Ql2[SEQ * QDIM];
__device__ __nv_bfloat16 g_Kh2[SEQ * KVDIM],  g_Kl2[SEQ * KVDIM];
__device__ __nv_bfloat16 g_Vh2[SEQ * KVDIM],  g_Vl2[SEQ * KVDIM];

// ---------------------------------------------------------------------------
// PTX helpers (base sm_100-safe)
// ---------------------------------------------------------------------------
__device__ __forceinline__ uint32_t smem_u32(const void* p) {
    uint32_t a;
    asm("{ .reg .u64 t; cvta.to.shared.u64 t, %1; cvt.u32.u64 %0, t; }"
        : "=r"(a) : "l"(p));
    return a;
}

__device__ __forceinline__ void ldsm4(uint32_t* r, uint32_t addr) {
    asm volatile("ldmatrix.sync.aligned.m8n8.x4.shared.b16 {%0,%1,%2,%3}, [%4];"
                 : "=r"(r[0]), "=r"(r[1]), "=r"(r[2]), "=r"(r[3]) : "r"(addr));
}

__device__ __forceinline__ void ldsm4t(uint32_t* r, uint32_t addr) {
    asm volatile("ldmatrix.sync.aligned.m8n8.x4.trans.shared.b16 {%0,%1,%2,%3}, [%4];"
                 : "=r"(r[0]), "=r"(r[1]), "=r"(r[2]), "=r"(r[3]) : "r"(addr));
}

__device__ __forceinline__ void mma16816(float* c, const uint32_t* a,
                                         uint32_t b0, uint32_t b1) {
    asm volatile(
        "mma.sync.aligned.m16n8k16.row.col.f32.bf16.bf16.f32 "
        "{%0,%1,%2,%3}, {%4,%5,%6,%7}, {%8,%9}, {%0,%1,%2,%3};"
        : "+f"(c[0]), "+f"(c[1]), "+f"(c[2]), "+f"(c[3])
        : "r"(a[0]), "r"(a[1]), "r"(a[2]), "r"(a[3]), "r"(b0), "r"(b1));
}

__device__ __forceinline__ uint32_t pack_bf16(float lo, float hi) {
    __nv_bfloat162 t;
    t.x = __float2bfloat16(lo);
    t.y = __float2bfloat16(hi);
    return *(uint32_t*)&t;
}

__device__ __forceinline__ void split2(float a, float b,
                                       __nv_bfloat162* h, __nv_bfloat162* l) {
    __nv_bfloat16 ha = __float2bfloat16(a);
    __nv_bfloat16 hb = __float2bfloat16(b);
    h->x = ha; h->y = hb;
    l->x = __float2bfloat16(a - __bfloat162float(ha));
    l->y = __float2bfloat16(b - __bfloat162float(hb));
}

// ---------------------------------------------------------------------------
// One fused fp32 -> (bf16 hi, bf16 lo) split for X + all 4 weights.
// ---------------------------------------------------------------------------
#define CVT_BLOCKS 49152

__global__ __launch_bounds__(256) void cvt_all(
    const float* __restrict__ x,  __nv_bfloat16* __restrict__ xh,  __nv_bfloat16* __restrict__ xl,
    const float* __restrict__ wq, __nv_bfloat16* __restrict__ wqh, __nv_bfloat16* __restrict__ wql,
    const float* __restrict__ wk, __nv_bfloat16* __restrict__ wkh, __nv_bfloat16* __restrict__ wkl,
    const float* __restrict__ wv, __nv_bfloat16* __restrict__ wvh, __nv_bfloat16* __restrict__ wvl,
    const float* __restrict__ wo, __nv_bfloat16* __restrict__ woh, __nv_bfloat16* __restrict__ wol)
{
    const int b = blockIdx.x;
    const float* src;
    __nv_bfloat16 *hi, *lo;
    int base;
    if (b < 8192)       { src = x;  hi = xh;  lo = xl;  base = 0; }
    else if (b < 24576) { src = wq; hi = wqh; lo = wql; base = 8192; }
    else if (b < 28672) { src = wk; hi = wkh; lo = wkl; base = 24576; }
    else if (b < 32768) { src = wv; hi = wvh; lo = wvl; base = 28672; }
    else                { src = wo; hi = woh; lo = wol; base = 32768; }

    const int i = ((b - base) * 256 + threadIdx.x) * 4;
    float4 v = *(const float4*)(src + i);
    __nv_bfloat162 h0, l0, h1, l1;
    split2(v.x, v.y, &h0, &l0);
    split2(v.z, v.w, &h1, &l1);
    *(__nv_bfloat162*)(hi + i)     = h0;
    *(__nv_bfloat162*)(hi + i + 2) = h1;
    *(__nv_bfloat162*)(lo + i)     = l0;
    *(__nv_bfloat162*)(lo + i + 2) = l1;
}

// ---------------------------------------------------------------------------
// mma.sync bf16x3 GEMM core, 512 threads (16 warps, 4x4 grid of 32x32 warp
// tiles), 128x128 CTA tile, BK=64, 3-stage cp.async pipeline.
// ---------------------------------------------------------------------------
#define GTHREADS 512
#define TILE_B   16384
#define STAGE_B  (4 * TILE_B)
#define GSM_TOTAL (3 * STAGE_B)          // 196608

__device__ __forceinline__ void load_tile64(
    uint32_t sdst, const __nv_bfloat16* __restrict__ g,
    int row0, int kc, int K, int tid)
{
#pragma unroll
    for (int s = 0; s < 2; s++) {
        int idx = tid + s * GTHREADS;
        int r = idx >> 3;
        int u = idx & 7;
        uint32_t sw = (uint32_t)(r * 128 + ((u ^ (r & 7)) << 4));
        const __nv_bfloat16* gp = g + (size_t)(row0 + r) * K + kc * 64 + u * 8;
        asm volatile("cp.async.cg.shared.global [%0], [%1], 16;"
                     :: "r"(sdst + sw), "l"(gp) : "memory");
    }
}

__device__ __forceinline__ void gemm_core(
    const __nv_bfloat16* __restrict__ Ahi, const __nv_bfloat16* __restrict__ Alo,
    const __nv_bfloat16* __restrict__ Bhi, const __nv_bfloat16* __restrict__ Blo,
    float* __restrict__ C,
    __nv_bfloat16* __restrict__ Chi, __nv_bfloat16* __restrict__ Clo,
    int N, int K, int bm, int bn, char* smem)
{
    const uint32_t sb = smem_u32(smem);
    const int tid  = threadIdx.x;
    const int lane = tid & 31;
    const int warp = tid >> 5;
    const int wm = warp >> 2;     // 0..3 -> row offset wm*32
    const int wn = warp & 3;      // 0..3 -> col offset wn*32
    const int NC = K >> 6;

    float acc[2][4][4];
#pragma unroll
    for (int i = 0; i < 2; i++)
#pragma unroll
        for (int j = 0; j < 4; j++)
#pragma unroll
            for (int q = 0; q < 4; q++) acc[i][j][q] = 0.0f;

    // Prologue: stages 0 and 1
#pragma unroll
    for (int c = 0; c < 2; c++) {
        uint32_t b = sb + c * STAGE_B;
        load_tile64(b,              Ahi, bm, c, K, tid);
        load_tile64(b + TILE_B,     Alo, bm, c, K, tid);
        load_tile64(b + 2 * TILE_B, Bhi, bn, c, K, tid);
        load_tile64(b + 3 * TILE_B, Blo, bn, c, K, tid);
        asm volatile("cp.async.commit_group;" ::: "memory");
    }

    const int a_r  = wm * 32 + (lane & 15);
    const int a_ku = lane >> 4;
    const int b_r  = wn * 32 + ((lane >> 3) & 1) * 8 + (lane & 7);
    const int b_ku = lane >> 4;

    int buf = 0;
    for (int c = 0; c < NC; c++) {
        if (c + 1 < NC)
            asm volatile("cp.async.wait_group 1;" ::: "memory");
        else
            asm volatile("cp.async.wait_group 0;" ::: "memory");
        __syncthreads();   // chunk c visible AND all warps done with chunk c-1

        if (c + 2 < NC) {
            int nb = buf + 2; if (nb >= 3) nb -= 3;
            uint32_t b2 = sb + nb * STAGE_B;
            load_tile64(b2,              Ahi, bm, c + 2, K, tid);
            load_tile64(b2 + TILE_B,     Alo, bm, c + 2, K, tid);
            load_tile64(b2 + 2 * TILE_B, Bhi, bn, c + 2, K, tid);
            load_tile64(b2 + 3 * TILE_B, Blo, bn, c + 2, K, tid);
            asm volatile("cp.async.commit_group;" ::: "memory");
        }

        const uint32_t b = sb + buf * STAGE_B;
        const uint32_t sAh = b;
        const uint32_t sAl = b + TILE_B;
        const uint32_t sBh = b + 2 * TILE_B;
        const uint32_t sBl = b + 3 * TILE_B;

#pragma unroll
        for (int ks = 0; ks < 4; ks++) {
            const int ku0 = ks * 2;
            uint32_t aH[2][4], aL[2][4];
#pragma unroll
            for (int mt = 0; mt < 2; mt++) {
                int r = a_r + mt * 16;
                int ku = ku0 + a_ku;
                uint32_t off = (uint32_t)(r * 128 + ((ku ^ (r & 7)) << 4));
                ldsm4(aH[mt], sAh + off);
                ldsm4(aL[mt], sAl + off);
            }
            uint32_t bH[2][4], bL[2][4];
#pragma unroll
            for (int ntp = 0; ntp < 2; ntp++) {
                int r = b_r + ntp * 16;
                int ku = ku0 + b_ku;
                uint32_t off = (uint32_t)(r * 128 + ((ku ^ (r & 7)) << 4));
                ldsm4(bH[ntp], sBh + off);
                ldsm4(bL[ntp], sBl + off);
            }
#pragma unroll
            for (int mt = 0; mt < 2; mt++) {
#pragma unroll
                for (int nt = 0; nt < 4; nt++) {
                    const int ntp = nt >> 1;
                    const int sel = nt & 1;
                    mma16816(acc[mt][nt], aH[mt], bH[ntp][sel], bH[ntp][sel + 2]);
                    mma16816(acc[mt][nt], aH[mt], bL[ntp][sel], bL[ntp][sel + 2]);
                    mma16816(acc[mt][nt], aL[mt], bH[ntp][sel], bH[ntp][sel + 2]);
                }
            }
        }
        if (++buf == 3) buf = 0;
    }

    // Epilogue
#pragma unroll
    for (int mt = 0; mt < 2; mt++) {
        const int row = bm + wm * 32 + mt * 16 + (lane >> 2);
#pragma unroll
        for (int nt = 0; nt < 4; nt++) {
            const int col = bn + wn * 32 + nt * 8 + (lane & 3) * 2;
            if (C) {
                *(float2*)(C + (size_t)row * N + col) =
                    make_float2(acc[mt][nt][0], acc[mt][nt][1]);
                *(float2*)(C + (size_t)(row + 8) * N + col) =
                    make_float2(acc[mt][nt][2], acc[mt][nt][3]);
            } else {
                __nv_bfloat162 h, l;
                split2(acc[mt][nt][0], acc[mt][nt][1], &h, &l);
                *(__nv_bfloat162*)(Chi + (size_t)row * N + col) = h;
                *(__nv_bfloat162*)(Clo + (size_t)row * N + col) = l;
                split2(acc[mt][nt][2], acc[mt][nt][3], &h, &l);
                *(__nv_bfloat162*)(Chi + (size_t)(row + 8) * N + col) = h;
                *(__nv_bfloat162*)(Clo + (size_t)(row + 8) * N + col) = l;
            }
        }
    }
}

// Plain GEMM kernel (Q-proj / O-proj)
__global__ __launch_bounds__(GTHREADS)
void gemm_bf16x3(
    const __nv_bfloat16* __restrict__ Ahi, const __nv_bfloat16* __restrict__ Alo,
    const __nv_bfloat16* __restrict__ Bhi, const __nv_bfloat16* __restrict__ Blo,
    float* __restrict__ C,
    __nv_bfloat16* __restrict__ Chi, __nv_bfloat16* __restrict__ Clo,
    int N, int K)
{
    extern __shared__ __align__(1024) char smem[];
    gemm_core(Ahi, Alo, Bhi, Blo, C, Chi, Clo, N, K,
              blockIdx.y * 128, blockIdx.x * 128, smem);
}

// Fused K+V projection: blockIdx.x < 8 -> K (fp32 out), else V (split out)
__global__ __launch_bounds__(GTHREADS)
void gemm_kv(
    const __nv_bfloat16* __restrict__ Ahi, const __nv_bfloat16* __restrict__ Alo,
    const __nv_bfloat16* __restrict__ Bkh, const __nv_bfloat16* __restrict__ Bkl,
    const __nv_bfloat16* __restrict__ Bvh, const __nv_bfloat16* __restrict__ Bvl,
    float* __restrict__ Ck,
    __nv_bfloat16* __restrict__ Cvh, __nv_bfloat16* __restrict__ Cvl)
{
    extern __shared__ __align__(1024) char smem[];
    const int bx = blockIdx.x;
    if (bx < KVDIM / 128) {
        gemm_core(Ahi, Alo, Bkh, Bkl, Ck, nullptr, nullptr, KVDIM, HID,
                  blockIdx.y * 128, bx * 128, smem);
    } else {
        gemm_core(Ahi, Alo, Bvh, Bvl, nullptr, Cvh, Cvl, KVDIM, HID,
                  blockIdx.y * 128, (bx - KVDIM / 128) * 128, smem);
    }
}

// ---------------------------------------------------------------------------
// Fused RMSNorm + RoPE for BOTH Q and K in one launch, bf16 hi/lo out.
// ---------------------------------------------------------------------------
#define RMS_BLOCKS (8192 + 2048)

__global__ __launch_bounds__(256) void rms_both(
    const float* __restrict__ Qf, const float* __restrict__ Kf,
    const float* __restrict__ qw, const float* __restrict__ kw,
    const float* __restrict__ cosb, const float* __restrict__ sinb,
    __nv_bfloat16* __restrict__ qh, __nv_bfloat16* __restrict__ ql,
    __nv_bfloat16* __restrict__ kh, __nv_bfloat16* __restrict__ kl)
{
    const int b = blockIdx.x;
    const float* X;
    const float* w;
    __nv_bfloat16 *oh, *ol;
    int nheads, row;
    if (b < 8192) { X = Qf; w = qw; oh = qh; ol = ql; nheads = NH;  row = b * 8; }
    else          { X = Kf; w = kw; oh = kh; ol = kl; nheads = NKV; row = (b - 8192) * 8; }
    row += threadIdx.x >> 5;
    const int lane = threadIdx.x & 31;
    const int s = row / nheads;

    const float* x = X + (size_t)row * HD;
    float4 v = *(const float4*)(x + lane * 4);

    float ss = v.x * v.x + v.y * v.y + v.z * v.z + v.w * v.w;
#pragma unroll
    for (int o = 16; o > 0; o >>= 1) ss += __shfl_xor_sync(0xffffffffu, ss, o);
    const float inv = rsqrtf(ss * (1.0f / 128.0f) + REPS);

    float4 wv = *(const float4*)(w + lane * 4);
    float x0 = v.x * inv * wv.x;
    float x1 = v.y * inv * wv.y;
    float x2 = v.z * inv * wv.z;
    float x3 = v.w * inv * wv.w;

    float p0 = __shfl_xor_sync(0xffffffffu, x0, 16);
    float p1 = __shfl_xor_sync(0xffffffffu, x1, 16);
    float p2 = __shfl_xor_sync(0xffffffffu, x2, 16);
    float p3 = __shfl_xor_sync(0xffffffffu, x3, 16);
    const float sgn = (lane < 16) ? -1.0f : 1.0f;

    const float* cp = cosb + (size_t)s * HD + lane * 4;
    const float* sp = sinb + (size_t)s * HD + lane * 4;
    float4 c = *(const float4*)cp;
    float4 sn = *(const float4*)sp;

    float o0 = x0 * c.x + sgn * p0 * sn.x;
    float o1 = x1 * c.y + sgn * p1 * sn.y;
    float o2 = x2 * c.z + sgn * p2 * sn.z;
    float o3 = x3 * c.w + sgn * p3 * sn.w;

    __nv_bfloat162 h, l;
    size_t base = (size_t)row * HD + lane * 4;
    split2(o0, o1, &h, &l);
    *(__nv_bfloat162*)(oh + base)     = h;
    *(__nv_bfloat162*)(ol + base)     = l;
    split2(o2, o3, &h, &l);
    *(__nv_bfloat162*)(oh + base + 2) = h;
    *(__nv_bfloat162*)(ol + base + 2) = l;
}

// ---------------------------------------------------------------------------
// Tensor-core flash attention (bf16 split), causal, GQA, 3-stage pipeline,
// single sync per KV block. Writes AO directly as bf16 hi/lo split.
// ---------------------------------------------------------------------------
#define KVTILE_B 16384                    // 64 rows x 256B
#define ASTAGE_B (4 * KVTILE_B)           // Kh,Kl,Vh,Vl
#define ASM_TOTAL (3 * ASTAGE_B)          // 196608

__device__ __forceinline__ uint32_t swz256(int r, int u) {
    return (uint32_t)(r * 256 + ((u ^ (r & 7)) << 4));
}

__device__ __forceinline__ void attn_load_kv(
    uint32_t base, const __nv_bfloat16* __restrict__ Kh,
    const __nv_bfloat16* __restrict__ Kl, const __nv_bfloat16* __restrict__ Vh,
    const __nv_bfloat16* __restrict__ Vl, int k0, int kvh, int tid)
{
#pragma unroll
    for (int t = 0; t < 4; t++) {
        int idx = tid + t * 256;
        int r = idx >> 4, u = idx & 15;
        size_t go = (size_t)(k0 + r) * KVDIM + kvh * HD + u * 8;
        uint32_t sw = swz256(r, u);
        asm volatile("cp.async.cg.shared.global [%0], [%1], 16;"
                     :: "r"(base + sw), "l"(Kh + go) : "memory");
        asm volatile("cp.async.cg.shared.global [%0], [%1], 16;"
                     :: "r"(base + KVTILE_B + sw), "l"(Kl + go) : "memory");
        asm volatile("cp.async.cg.shared.global [%0], [%1], 16;"
                     :: "r"(base + 2 * KVTILE_B + sw), "l"(Vh + go) : "memory");
        asm volatile("cp.async.cg.shared.global [%0], [%1], 16;"
                     :: "r"(base + 3 * KVTILE_B + sw), "l"(Vl + go) : "memory");
    }
}

__global__ __launch_bounds__(256, 1)
void attn_mma(const __nv_bfloat16* __restrict__ Qh, const __nv_bfloat16* __restrict__ Ql,
              const __nv_bfloat16* __restrict__ Kh, const __nv_bfloat16* __restrict__ Kl,
              const __nv_bfloat16* __restrict__ Vh, const __nv_bfloat16* __restrict__ Vl,
              __nv_bfloat16* __restrict__ Ohi, __nv_bfloat16* __restrict__ Olo)
{
    extern __shared__ __align__(1024) char smem[];
    const uint32_t sb = smem_u32(smem);
    const int tid  = threadIdx.x;
    const int lane = tid & 31;
    const int warp = tid >> 5;
    const int qb = (int)gridDim.x - 1 - (int)blockIdx.x;
    const int h  = blockIdx.y;
    const int kvh = h >> 2;
    const int q0 = qb * 128;
    const int NB = 2 * qb + 2;

    // ---- Stage Q through smem, build register fragments (hi then lo)
    uint32_t qfh[8][4], qfl[8][4];
#pragma unroll
    for (int comp = 0; comp < 2; comp++) {
        const __nv_bfloat16* src = comp ? Ql : Qh;
        for (int t = 0; t < 8; t++) {
            int idx = tid + t * 256;
            int r = idx >> 4, u = idx & 15;
            const __nv_bfloat16* gp = src + (size_t)(q0 + r) * QDIM + h * HD + u * 8;
            asm volatile("cp.async.cg.shared.global [%0], [%1], 16;"
                         :: "r"(sb + swz256(r, u)), "l"(gp) : "memory");
        }
        asm volatile("cp.async.commit_group;" ::: "memory");
        asm volatile("cp.async.wait_group 0;" ::: "memory");
        __syncthreads();
        {
            int r = warp * 16 + (lane & 15);
#pragma unroll
            for (int ks = 0; ks < 8; ks++) {
                uint32_t addr = sb + swz256(r, 2 * ks + (lane >> 4));
                if (comp) ldsm4(qfl[ks], addr);
                else      ldsm4(qfh[ks], addr);
            }
        }
        __syncthreads();
    }

    float o[16][4];
#pragma unroll
    for (int i = 0; i < 16; i++)
#pragma unroll
        for (int q = 0; q < 4; q++) o[i][q] = 0.0f;
    float m0 = -1e30f, m1 = -1e30f, l0 = 0.0f, l1 = 0.0f;

    const int row0 = q0 + warp * 16 + (lane >> 2);
    const int row1 = row0 + 8;

    // ---- prologue: stages 0 and 1
    attn_load_kv(sb, Kh, Kl, Vh, Vl, 0, kvh, tid);
    asm volatile("cp.async.commit_group;" ::: "memory");
    if (NB > 1) {
        attn_load_kv(sb + ASTAGE_B, Kh, Kl, Vh, Vl, 64, kvh, tid);
        asm volatile("cp.async.commit_group;" ::: "memory");
    }

    int buf = 0;
    for (int kb = 0; kb < NB; kb++) {
        if (kb + 1 < NB)
            asm volatile("cp.async.wait_group 1;" ::: "memory");
        else
            asm volatile("cp.async.wait_group 0;" ::: "memory");
        __syncthreads();   // block kb visible AND all warps done with block kb-1

        if (kb + 2 < NB) {
            int nb = buf + 2; if (nb >= 3) nb -= 3;
            attn_load_kv(sb + nb * ASTAGE_B, Kh, Kl, Vh, Vl, (kb + 2) * 64, kvh, tid);
            asm volatile("cp.async.commit_group;" ::: "memory");
        }

        const uint32_t bK = sb + buf * ASTAGE_B;
        const int k0 = kb * 64;

        // ---- S = Q K^T (bf16x3)
        float s[8][4];
#pragma unroll
        for (int nt = 0; nt < 8; nt++)
#pragma unroll
            for (int q = 0; q < 4; q++) s[nt][q] = 0.0f;

#pragma unroll
        for (int ks = 0; ks < 8; ks++) {
#pragma unroll
            for (int g = 0; g < 4; g++) {
                uint32_t kh4[4], kl4[4];
                int rr = g * 16 + ((lane >> 3) & 1) * 8 + (lane & 7);
                uint32_t off = swz256(rr, 2 * ks + (lane >> 4));
                ldsm4(kh4, bK + off);
                ldsm4(kl4, bK + KVTILE_B + off);
#pragma unroll
                for (int sel = 0; sel < 2; sel++) {
                    int nt = g * 2 + sel;
                    mma16816(s[nt], qfh[ks], kh4[sel], kh4[sel + 2]);
                    mma16816(s[nt], qfh[ks], kl4[sel], kl4[sel + 2]);
                    mma16816(s[nt], qfl[ks], kh4[sel], kh4[sel + 2]);
                }
            }
        }

        // ---- scale + causal mask
        const bool domask = (k0 + 63) > row0;
#pragma unroll
        for (int nt = 0; nt < 8; nt++) {
            int c0 = k0 + nt * 8 + (lane & 3) * 2;
#pragma unroll
            for (int q = 0; q < 4; q++) s[nt][q] *= RSCALE;
            if (domask) {
                if (c0     > row0) s[nt][0] = -1e30f;
                if (c0 + 1 > row0) s[nt][1] = -1e30f;
                if (c0     > row1) s[nt][2] = -1e30f;
                if (c0 + 1 > row1) s[nt][3] = -1e30f;
            }
        }

        // ---- online softmax
        float mx0 = -1e30f, mx1 = -1e30f;
#pragma unroll
        for (int nt = 0; nt < 8; nt++) {
            mx0 = fmaxf(mx0, fmaxf(s[nt][0], s[nt][1]));
            mx1 = fmaxf(mx1, fmaxf(s[nt][2], s[nt][3]));
        }
        mx0 = fmaxf(mx0, __shfl_xor_sync(0xffffffffu, mx0, 1));
        mx0 = fmaxf(mx0, __shfl_xor_sync(0xffffffffu, mx0, 2));
        mx1 = fmaxf(mx1, __shfl_xor_sync(0xffffffffu, mx1, 1));
        mx1 = fmaxf(mx1, __shfl_xor_sync(0xffffffffu, mx1, 2));

        float mn0 = fmaxf(m0, mx0), mn1 = fmaxf(m1, mx1);
        float a0 = __expf(m0 - mn0), a1 = __expf(m1 - mn1);
        m0 = mn0; m1 = mn1;

        float sum0 = 0.0f, sum1 = 0.0f;
#pragma unroll
        for (int nt = 0; nt < 8; nt++) {
            s[nt][0] = __expf(s[nt][0] - mn0);
            s[nt][1] = __expf(s[nt][1] - mn0);
            s[nt][2] = __expf(s[nt][2] - mn1);
            s[nt][3] = __expf(s[nt][3] - mn1);
            sum0 += s[nt][0] + s[nt][1];
            sum1 += s[nt][2] + s[nt][3];
        }
        sum0 += __shfl_xor_sync(0xffffffffu, sum0, 1);
        sum0 += __shfl_xor_sync(0xffffffffu, sum0, 2);
        sum1 += __shfl_xor_sync(0xffffffffu, sum1, 1);
        sum1 += __shfl_xor_sync(0xffffffffu, sum1, 2);
        l0 = l0 * a0 + sum0;
        l1 = l1 * a1 + sum1;

#pragma unroll
        for (int nt = 0; nt < 16; nt++) {
            o[nt][0] *= a0; o[nt][1] *= a0;
            o[nt][2] *= a1; o[nt][3] *= a1;
        }

        // ---- O += P V (bf16 split P and V)
#pragma unroll
        for (int kt = 0; kt < 4; kt++) {
            uint32_t pah[4], pal[4];
            {
                float e[8] = { s[2*kt][0], s[2*kt][1], s[2*kt][2], s[2*kt][3],
                               s[2*kt+1][0], s[2*kt+1][1], s[2*kt+1][2], s[2*kt+1][3] };
                float hf[8], lf[8];
#pragma unroll
                for (int q = 0; q < 8; q++) {
                    __nv_bfloat16 hb = __float2bfloat16(e[q]);
                    hf[q] = __bfloat162float(hb);
                    lf[q] = e[q] - hf[q];
                }
                pah[0] = pack_bf16(hf[0], hf[1]);
                pah[1] = pack_bf16(hf[2], hf[3]);
                pah[2] = pack_bf16(hf[4], hf[5]);
                pah[3] = pack_bf16(hf[6], hf[7]);
                pal[0] = pack_bf16(lf[0], lf[1]);
                pal[1] = pack_bf16(lf[2], lf[3]);
                pal[2] = pack_bf16(lf[4], lf[5]);
                pal[3] = pack_bf16(lf[6], lf[7]);
            }
            const int j = lane >> 3, ll = lane & 7;
            const int rr = kt * 16 + (j & 1) * 8 + ll;
#pragma unroll
            for (int gn = 0; gn < 8; gn++) {
                uint32_t vh4[4], vl4[4];
                uint32_t off = swz256(rr, gn * 2 + (j >> 1));
                ldsm4t(vh4, bK + 2 * KVTILE_B + off);
                ldsm4t(vl4, bK + 3 * KVTILE_B + off);
#pragma unroll
                for (int sel = 0; sel < 2; sel++) {
                    int nt = gn * 2 + sel;
                    mma16816(o[nt], pah, vh4[sel * 2], vh4[sel * 2 + 1]);
                    mma16816(o[nt], pah, vl4[sel * 2], vl4[sel * 2 + 1]);
                    mma16816(o[nt], pal, vh4[sel * 2], vh4[sel * 2 + 1]);
                }
            }
        }
        if (++buf == 3) buf = 0;
    }

    // ---- finalize: write split AO directly
    const float i0 = 1.0f / l0, i1 = 1.0f / l1;
#pragma unroll
    for (int nt = 0; nt < 16; nt++) {
        int col = h * HD + nt * 8 + (lane & 3) * 2;
        __nv_bfloat162 hh, ll2;
        split2(o[nt][0] * i0, o[nt][1] * i0, &hh, &ll2);
        *(__nv_bfloat162*)(Ohi + (size_t)row0 * QDIM + col) = hh;
        *(__nv_bfloat162*)(Olo + (size_t)row0 * QDIM + col) = ll2;
        split2(o[nt][2] * i1, o[nt][3] * i1, &hh, &ll2);
        *(__nv_bfloat162*)(Ohi + (size_t)row1 * QDIM + col) = hh;
        *(__nv_bfloat162*)(Olo + (size_t)row1 * QDIM + col) = ll2;
    }
}

// ---------------------------------------------------------------------------
extern "C" void kernel_launch(void* const* d_in, const int* in_sizes, int n_in,
                              void* d_out, int out_size)
{
    const float* hidden = (const float*)d_in[0];
    const float* cosb   = (const float*)d_in[1];
    const float* sinb   = (const float*)d_in[2];
    const float* Wq     = (const float*)d_in[3];
    const float* Wk     = (const float*)d_in[4];
    const float* Wv     = (const float*)d_in[5];
    const float* Wo     = (const float*)d_in[6];
    const float* qw     = (const float*)d_in[7];
    const float* kw     = (const float*)d_in[8];
    float* out = (float*)d_out;

    float *Qp, *Kp;
    cudaGetSymbolAddress((void**)&Qp,  g_Q);
    cudaGetSymbolAddress((void**)&Kp,  g_K);

    __nv_bfloat16 *Xh, *Xl, *Wqh, *Wql, *Wkh, *Wkl, *Wvh, *Wvl, *Woh, *Wol, *AOh, *AOl;
    __nv_bfloat16 *Qh2, *Ql2, *Kh2, *Kl2, *Vh2, *Vl2;
    cudaGetSymbolAddress((void**)&Xh,  g_Xhi);  cudaGetSymbolAddress((void**)&Xl,  g_Xlo);
    cudaGetSymbolAddress((void**)&Wqh, g_Wqh);  cudaGetSymbolAddress((void**)&Wql, g_Wql);
    cudaGetSymbolAddress((void**)&Wkh, g_Wkh);  cudaGetSymbolAddress((void**)&Wkl, g_Wkl);
    cudaGetSymbolAddress((void**)&Wvh, g_Wvh);  cudaGetSymbolAddress((void**)&Wvl, g_Wvl);
    cudaGetSymbolAddress((void**)&Woh, g_Woh);  cudaGetSymbolAddress((void**)&Wol, g_Wol);
    cudaGetSymbolAddress((void**)&AOh, g_AOh);  cudaGetSymbolAddress((void**)&AOl, g_AOl);
    cudaGetSymbolAddress((void**)&Qh2, g_Qh2);  cudaGetSymbolAddress((void**)&Ql2, g_Ql2);
    cudaGetSymbolAddress((void**)&Kh2, g_Kh2);  cudaGetSymbolAddress((void**)&Kl2, g_Kl2);
    cudaGetSymbolAddress((void**)&Vh2, g_Vh2);  cudaGetSymbolAddress((void**)&Vl2, g_Vl2);

    cudaFuncSetAttribute(gemm_bf16x3,
                         cudaFuncAttributeMaxDynamicSharedMemorySize, GSM_TOTAL);
    cudaFuncSetAttribute(gemm_kv,
                         cudaFuncAttributeMaxDynamicSharedMemorySize, GSM_TOTAL);
    cudaFuncSetAttribute(attn_mma,
                         cudaFuncAttributeMaxDynamicSharedMemorySize, ASM_TOTAL);

    // L0: all split conversions in one launch
    cvt_all<<<CVT_BLOCKS, 256>>>(hidden, Xh, Xl, Wq, Wqh, Wql, Wk, Wkh, Wkl,
                                 Wv, Wvh, Wvl, Wo, Woh, Wol);

    // L1: Q projection
    gemm_bf16x3<<<dim3(QDIM / 128, SEQ / 128), GTHREADS, GSM_TOTAL>>>(
        Xh, Xl, Wqh, Wql, Qp, nullptr, nullptr, QDIM, HID);

    // L2: fused K+V projection
    gemm_kv<<<dim3(2 * KVDIM / 128, SEQ / 128), GTHREADS, GSM_TOTAL>>>(
        Xh, Xl, Wkh, Wkl, Wvh, Wvl, Kp, Vh2, Vl2);

    // L3: RMSNorm + RoPE for Q and K in one launch
    rms_both<<<RMS_BLOCKS, 256>>>(Qp, Kp, qw, kw, cosb, sinb,
                                  Qh2, Ql2, Kh2, Kl2);

    // L4: tensor-core flash attention -> split AO
    attn_mma<<<dim3(SEQ / 128, NH), 256, ASM_TOTAL>>>(
        Qh2, Ql2, Kh2, Kl2, Vh2, Vl2, AOh, AOl);

    // L5: output projection
    gemm_bf16x3<<<dim3(HID / 128, SEQ / 128), GTHREADS, GSM_TOTAL>>>(
        AOh, AOl, Woh, Wol, out, nullptr, nullptr, HID, QDIM);
}